// round 5
// baseline (speedup 1.0000x reference)
#include <cuda_runtime.h>
#include <cuda_bf16.h>
#include <math.h>

#define N_NODES_MAX 100000
#define E_MAX       1600000
#define HID 32
#define IN_DIM 4
#define N_GRAPHS_MAX 64
#define EPSV 1e-5f

#define SCAN_BS 256
#define SCAN_BLOCKS ((N_NODES_MAX + SCAN_BS - 1) / SCAN_BS)   // 391
#define NPAD (SCAN_BLOCKS * SCAN_BS)                          // 100096
#define EB 256
#define MAX_EBLOCKS ((E_MAX + EB - 1) / EB + 1)

typedef unsigned long long ull;

// ---------------- static device scratch ----------------
__device__ float g_agg[N_NODES_MAX * HID];
__device__ float g_stats[2 * HID];
__device__ float g_gsum[N_GRAPHS_MAX * HID];
__device__ int   g_gcnt[N_GRAPHS_MAX];
__device__ int   g_done;

__device__ int g_cnt[NPAD];
__device__ int g_offs[N_NODES_MAX + 1];
__device__ int g_cursor[NPAD];
__device__ int2 g_esorted[E_MAX];               // (src, dst) sorted by dst
__device__ int g_bstart[MAX_EBLOCKS];

__device__ int g_scan_flag[SCAN_BLOCKS];        // 0=invalid 1=local 2=inclusive
__device__ int g_scan_val[SCAN_BLOCKS];
__device__ int g_scan_inc[SCAN_BLOCKS];

// ---------------- helpers ----------------
__device__ __forceinline__ void atomicMaxFloat(float* addr, float v) {
    int vi = __float_as_int(v);
    if (vi >= 0) atomicMax((int*)addr, vi);
    else         atomicMin((unsigned int*)addr, (unsigned int)vi);
}
__device__ __forceinline__ ull fma2(ull a, ull b, ull c) {
    ull d;
    asm("fma.rn.f32x2 %0, %1, %2, %3;" : "=l"(d) : "l"(a), "l"(b), "l"(c));
    return d;
}
__device__ __forceinline__ ull dup2(float v) {
    ull d;
    asm("mov.b64 %0, {%1, %1};" : "=l"(d) : "f"(v));
    return d;
}
__device__ __forceinline__ void unpack2(ull p, float& lo, float& hi) {
    asm("mov.b64 {%0, %1}, %2;" : "=f"(lo), "=f"(hi) : "l"(p));
}

// ---------------- kernel 1: zero small scratch ----------------
__global__ void zero_kernel(int n_graphs) {
    int i = blockIdx.x * blockDim.x + threadIdx.x;
    if (i < NPAD) g_cnt[i] = 0;
    if (i < SCAN_BLOCKS) g_scan_flag[i] = 0;
    if (i < 2 * HID) g_stats[i] = 0.f;
    if (i < n_graphs * HID) g_gsum[i] = 0.f;
    if (i < n_graphs) g_gcnt[i] = 0;
    if (i == 0) g_done = 0;
}

// ---------------- kernel 2: histogram of dst + g_agg -inf init ----------------
__global__ void hist_kernel(const int* __restrict__ ei, int E, int n_nodes) {
    int e = blockIdx.x * blockDim.x + threadIdx.x;
    if (e < E) atomicAdd(&g_cnt[ei[E + e]], 1);
    const float ninf = __int_as_float(0xFF800000);
    int tot2 = n_nodes * HID / 2;
    int stride = gridDim.x * blockDim.x;
    for (int i = e; i < tot2; i += stride)
        reinterpret_cast<float2*>(g_agg)[i] = make_float2(ninf, ninf);
}

// ---------------- kernel 3: single-pass scan (decoupled lookback) ----------------
__global__ void scan_kernel(int n, int E) {
    __shared__ int s[SCAN_BS];
    __shared__ int s_prefix;
    int t = threadIdx.x, b = blockIdx.x;
    int i = b * SCAN_BS + t;
    int v = (i < n) ? g_cnt[i] : 0;
    s[t] = v;
    __syncthreads();
    #pragma unroll
    for (int off = 1; off < SCAN_BS; off <<= 1) {
        int tv = (t >= off) ? s[t - off] : 0;
        __syncthreads();
        s[t] += tv;
        __syncthreads();
    }
    int total = s[SCAN_BS - 1];
    if (t == 0) {
        if (b == 0) {
            g_scan_inc[0] = total;
            __threadfence();
            g_scan_flag[0] = 2;
            s_prefix = 0;
        } else {
            g_scan_val[b] = total;
            __threadfence();
            g_scan_flag[b] = 1;
            int sum = 0;
            for (int p = b - 1; p >= 0; p--) {
                int f;
                do { f = ((volatile int*)g_scan_flag)[p]; } while (f == 0);
                __threadfence();
                if (f == 2) { sum += ((volatile int*)g_scan_inc)[p]; break; }
                sum += ((volatile int*)g_scan_val)[p];
            }
            g_scan_inc[b] = sum + total;
            __threadfence();
            g_scan_flag[b] = 2;
            s_prefix = sum;
        }
    }
    __syncthreads();
    int excl = s_prefix + s[t] - v;
    if (i < n) { g_offs[i] = excl; g_cursor[i] = excl; }
    if (i == 0) g_offs[n] = E;
}

// ---------------- kernel 4: scatter (src,dst) + per-block bstart search ----------------
__global__ void scatter_kernel(const int* __restrict__ ei, int E, int n_nodes) {
    int e = blockIdx.x * blockDim.x + threadIdx.x;
    if (e < E) {
        int sN = ei[e];
        int d = ei[E + e];
        int pos = atomicAdd(&g_cursor[d], 1);
        g_esorted[pos] = make_int2(sN, d);
    }
    if (threadIdx.x == 0) {
        // max node n with offs[n] <= blockIdx.x * EB   (grid size == eblocks)
        int target = blockIdx.x * EB;
        int lo = 0, hi = n_nodes;
        while (lo < hi) {
            int mid = (lo + hi + 1) >> 1;
            if (g_offs[mid] <= target) lo = mid; else hi = mid - 1;
        }
        g_bstart[blockIdx.x] = lo;
    }
}

// ---------------- kernel 5: edge MLP (f32x2, 16B weight loads) + segmented max ----------------
__global__ void __launch_bounds__(EB) edge2_kernel(
    const float* __restrict__ x,
    const float* __restrict__ W1, const float* __restrict__ b1,
    const float* __restrict__ W2, const float* __restrict__ b2,
    int E, int n_nodes)
{
    __shared__ __align__(16) float sW1[2 * IN_DIM * HID];
    __shared__ __align__(16) float sW2[HID * HID];
    __shared__ __align__(16) float sb1[HID];
    __shared__ __align__(16) float sb2[HID];
    __shared__ float sOut[EB][HID + 1];

    const int tid = threadIdx.x;
    for (int i = tid; i < 2 * IN_DIM * HID; i += EB) sW1[i] = W1[i];
    for (int i = tid; i < HID * HID; i += EB)        sW2[i] = W2[i];
    if (tid < HID) { sb1[tid] = b1[tid]; sb2[tid] = b2[tid]; }
    __syncthreads();

    const int e0 = blockIdx.x * EB;
    const int e1 = min(e0 + EB, E);
    const int e  = e0 + tid;

    if (e < E) {
        const int2 sd = g_esorted[e];
        const float4 xi = __ldg(reinterpret_cast<const float4*>(x + (size_t)sd.y * IN_DIM));
        const float4 xj = __ldg(reinterpret_cast<const float4*>(x + (size_t)sd.x * IN_DIM));

        float msg[8];
        msg[0] = xi.x; msg[1] = xi.y; msg[2] = xi.z; msg[3] = xi.w;
        msg[4] = xj.x - xi.x; msg[5] = xj.y - xi.y; msg[6] = xj.z - xi.z; msg[7] = xj.w - xi.w;

        const ulonglong2* b1p = reinterpret_cast<const ulonglong2*>(sb1);
        const ulonglong2* b2p = reinterpret_cast<const ulonglong2*>(sb2);

        // layer 1: 16 packed accumulators, weights via 16B LDS
        ull hp[16];
        #pragma unroll
        for (int q = 0; q < 8; q++) {
            ulonglong2 bv = b1p[q];
            hp[2 * q] = bv.x; hp[2 * q + 1] = bv.y;
        }
        #pragma unroll
        for (int k = 0; k < 8; k++) {
            ull md = dup2(msg[k]);
            const ulonglong2* w1p = reinterpret_cast<const ulonglong2*>(sW1 + k * HID);
            #pragma unroll
            for (int q = 0; q < 8; q++) {
                ulonglong2 wv = w1p[q];
                hp[2 * q]     = fma2(md, wv.x, hp[2 * q]);
                hp[2 * q + 1] = fma2(md, wv.y, hp[2 * q + 1]);
            }
        }
        float h[32];
        #pragma unroll
        for (int cc = 0; cc < 16; cc++) {
            float lo, hi;
            unpack2(hp[cc], lo, hi);
            h[2 * cc]     = fmaxf(lo, 0.f);
            h[2 * cc + 1] = fmaxf(hi, 0.f);
        }

        // layer 2
        ull op[16];
        #pragma unroll
        for (int q = 0; q < 8; q++) {
            ulonglong2 bv = b2p[q];
            op[2 * q] = bv.x; op[2 * q + 1] = bv.y;
        }
        #pragma unroll
        for (int j = 0; j < HID; j++) {
            ull hd = dup2(h[j]);
            const ulonglong2* w2p = reinterpret_cast<const ulonglong2*>(sW2 + j * HID);
            #pragma unroll
            for (int q = 0; q < 8; q++) {
                ulonglong2 wv = w2p[q];
                op[2 * q]     = fma2(hd, wv.x, op[2 * q]);
                op[2 * q + 1] = fma2(hd, wv.y, op[2 * q + 1]);
            }
        }

        #pragma unroll
        for (int cc = 0; cc < 16; cc++) {
            float lo, hi;
            unpack2(op[cc], lo, hi);
            sOut[tid][2 * cc]     = lo;
            sOut[tid][2 * cc + 1] = hi;
        }
    }
    __syncthreads();

    // segmented max over this block's edge range
    const int c = tid & 31;
    const int w = tid >> 5;
    const int nf = g_bstart[blockIdx.x];
    for (int n = nf + w; n < n_nodes; n += 8) {
        const int on = g_offs[n];
        if (on >= e1) break;
        const int on1 = g_offs[n + 1];
        const int eb = max(on, e0);
        const int ee = min(on1, e1);
        float m = -INFINITY;
        for (int k = eb; k < ee; k++) m = fmaxf(m, sOut[k - e0][c]);
        const bool interior = (on >= e0) && (on1 <= e1);
        if (interior) {
            g_agg[(size_t)n * HID + c] = m;
        } else if (eb < ee) {
            atomicMaxFloat(&g_agg[(size_t)n * HID + c], m);
        }
    }
}

// ---------------- kernel 6: BN stats (float4 reads, sanitize on read) ----------------
__global__ void __launch_bounds__(256) stats_kernel(int n_nodes) {
    int t = threadIdx.x;
    float4 sum = make_float4(0.f, 0.f, 0.f, 0.f);
    float4 sq  = make_float4(0.f, 0.f, 0.f, 0.f);
    int tot4 = n_nodes * HID / 4;
    const float4* agg4 = reinterpret_cast<const float4*>(g_agg);
    for (int i = blockIdx.x * blockDim.x + t; i < tot4; i += gridDim.x * blockDim.x) {
        float4 v = agg4[i];
        if (!isfinite(v.x)) v.x = 0.f;
        if (!isfinite(v.y)) v.y = 0.f;
        if (!isfinite(v.z)) v.z = 0.f;
        if (!isfinite(v.w)) v.w = 0.f;
        sum.x += v.x; sum.y += v.y; sum.z += v.z; sum.w += v.w;
        sq.x += v.x * v.x; sq.y += v.y * v.y; sq.z += v.z * v.z; sq.w += v.w * v.w;
    }
    // channel group of thread t is 4*(t%8) .. +3 (stride multiple of 8 float4 = 32 ch)
    __shared__ float4 sS[256], sQ[256];
    sS[t] = sum; sQ[t] = sq;
    __syncthreads();
    #pragma unroll
    for (int s = 128; s >= 8; s >>= 1) {
        if (t < s) {
            float4 a = sS[t], b = sS[t + s];
            sS[t] = make_float4(a.x + b.x, a.y + b.y, a.z + b.z, a.w + b.w);
            float4 c = sQ[t], d = sQ[t + s];
            sQ[t] = make_float4(c.x + d.x, c.y + d.y, c.z + d.z, c.w + d.w);
        }
        __syncthreads();
    }
    if (t < 8) {
        int cb = 4 * t;
        float4 a = sS[t], c = sQ[t];
        atomicAdd(&g_stats[cb + 0], a.x); atomicAdd(&g_stats[cb + 1], a.y);
        atomicAdd(&g_stats[cb + 2], a.z); atomicAdd(&g_stats[cb + 3], a.w);
        atomicAdd(&g_stats[HID + cb + 0], c.x); atomicAdd(&g_stats[HID + cb + 1], c.y);
        atomicAdd(&g_stats[HID + cb + 2], c.z); atomicAdd(&g_stats[HID + cb + 3], c.w);
    }
}

// ---------------- kernel 7: BN fold + normalize + relu + pool + (last block) readout ----------------
__global__ void __launch_bounds__(256) pool_final_kernel(
    const int* __restrict__ batch, int n_nodes,
    const float* __restrict__ gamma, const float* __restrict__ beta,
    const float* __restrict__ Wr1, const float* __restrict__ br1,
    const float* __restrict__ Wr2, const float* __restrict__ br2,
    float* __restrict__ out, int n_graphs)
{
    const int c = threadIdx.x & 31;
    const int w = threadIdx.x >> 5;

    // fold BN per-thread (cheap, redundant per block)
    float inv_n = 1.f / (float)n_nodes;
    float mean = g_stats[c] * inv_n;
    float var = g_stats[HID + c] * inv_n - mean * mean;
    float sc = gamma[c] * rsqrtf(var + EPSV);
    float sh = beta[c] - mean * sc;

    int chunk = (n_nodes + gridDim.x - 1) / gridDim.x;
    int n0 = blockIdx.x * chunk;
    int n1 = min(n0 + chunk, n_nodes);

    float acc = 0.f;
    int cur = -1;
    int cnt = 0;
    for (int n = n0 + w; n < n1; n += 8) {
        int g = batch[n];
        float v = g_agg[(size_t)n * HID + c];
        if (!isfinite(v)) v = 0.f;
        v = fmaxf(v * sc + sh, 0.f);
        if (g != cur) {
            if (cur >= 0) {
                atomicAdd(&g_gsum[cur * HID + c], acc);
                if (c == 0) atomicAdd(&g_gcnt[cur], cnt);
            }
            cur = g; acc = 0.f; cnt = 0;
        }
        acc += v; cnt++;
    }
    if (cur >= 0) {
        atomicAdd(&g_gsum[cur * HID + c], acc);
        if (c == 0) atomicAdd(&g_gcnt[cur], cnt);
    }

    // last-block-done runs the readout MLP
    __shared__ int s_last;
    __threadfence();
    __syncthreads();
    if (threadIdx.x == 0) {
        int ticket = atomicAdd(&g_done, 1);
        s_last = (ticket == gridDim.x - 1);
    }
    __syncthreads();
    if (s_last) {
        __threadfence();
        int g = threadIdx.x;
        if (g < n_graphs) {
            float inv_cnt = 1.f / fmaxf((float)g_gcnt[g], 1.f);
            float p[HID];
            #pragma unroll
            for (int k = 0; k < HID; k++) p[k] = g_gsum[g * HID + k] * inv_cnt;
            float h[16];
            #pragma unroll
            for (int m = 0; m < 16; m++) {
                float a = br1[m];
                #pragma unroll
                for (int k = 0; k < HID; k++) a += p[k] * Wr1[k * 16 + m];
                h[m] = fmaxf(a, 0.f);
            }
            float o = br2[0];
            #pragma unroll
            for (int m = 0; m < 16; m++) o += h[m] * Wr2[m];
            out[g] = o;
        }
    }
}

// ---------------- launch ----------------
extern "C" void kernel_launch(void* const* d_in, const int* in_sizes, int n_in,
                              void* d_out, int out_size) {
    const float* x     = (const float*)d_in[0];
    const int*   ei    = (const int*)d_in[1];
    const int*   batch = (const int*)d_in[2];
    const float* W1    = (const float*)d_in[3];
    const float* b1    = (const float*)d_in[4];
    const float* W2    = (const float*)d_in[5];
    const float* b2    = (const float*)d_in[6];
    const float* gamma = (const float*)d_in[7];
    const float* beta  = (const float*)d_in[8];
    const float* Wr1   = (const float*)d_in[9];
    const float* br1   = (const float*)d_in[10];
    const float* Wr2   = (const float*)d_in[11];
    const float* br2   = (const float*)d_in[12];
    float* out = (float*)d_out;

    int E        = in_sizes[1] / 2;
    int n_nodes  = in_sizes[2];
    int n_graphs = out_size;
    int eblocks  = (E + EB - 1) / EB;

    zero_kernel<<<(NPAD + 255) / 256, 256>>>(n_graphs);
    hist_kernel<<<(E + 255) / 256, 256>>>(ei, E, n_nodes);
    scan_kernel<<<SCAN_BLOCKS, SCAN_BS>>>(n_nodes, E);
    scatter_kernel<<<eblocks, EB>>>(ei, E, n_nodes);
    edge2_kernel<<<eblocks, EB>>>(x, W1, b1, W2, b2, E, n_nodes);
    stats_kernel<<<592, 256>>>(n_nodes);
    pool_final_kernel<<<256, 256>>>(batch, n_nodes, gamma, beta, Wr1, br1, Wr2, br2, out, n_graphs);
}

// round 6
// speedup vs baseline: 1.0785x; 1.0785x over previous
#include <cuda_runtime.h>
#include <cuda_bf16.h>
#include <math.h>

#define N_NODES_MAX 100000
#define E_MAX       1600000
#define HID 32
#define IN_DIM 4
#define N_GRAPHS_MAX 64
#define EPSV 1e-5f

#define SCAN_BS 256
#define SCAN_BLOCKS ((N_NODES_MAX + SCAN_BS - 1) / SCAN_BS)   // 391
#define NPAD (SCAN_BLOCKS * SCAN_BS)                          // 100096
#define EB 256
#define MAX_EBLOCKS ((E_MAX + EB - 1) / EB + 1)

typedef unsigned long long ull;

// ---------------- static device scratch ----------------
__device__ float g_agg[N_NODES_MAX * HID];
__device__ float g_u[N_NODES_MAX * HID];        // per-node u = x@(A-B) + b1
__device__ float g_stats[2 * HID];
__device__ float g_gsum[N_GRAPHS_MAX * HID];
__device__ int   g_gcnt[N_GRAPHS_MAX];
__device__ int   g_done;

__device__ int g_cnt[NPAD];
__device__ int g_excl[NPAD];
__device__ int g_bsum[SCAN_BLOCKS];
__device__ int g_bscan[SCAN_BLOCKS];
__device__ int g_offs[N_NODES_MAX + 1];
__device__ int g_cursor[NPAD];
__device__ int2 g_esorted[E_MAX];               // (src, dst) sorted by dst
__device__ int g_bstart[MAX_EBLOCKS];

// ---------------- helpers ----------------
__device__ __forceinline__ void atomicMaxFloat(float* addr, float v) {
    int vi = __float_as_int(v);
    if (vi >= 0) atomicMax((int*)addr, vi);
    else         atomicMin((unsigned int*)addr, (unsigned int)vi);
}
__device__ __forceinline__ ull fma2(ull a, ull b, ull c) {
    ull d;
    asm("fma.rn.f32x2 %0, %1, %2, %3;" : "=l"(d) : "l"(a), "l"(b), "l"(c));
    return d;
}
__device__ __forceinline__ ull dup2(float v) {
    ull d;
    asm("mov.b64 %0, {%1, %1};" : "=l"(d) : "f"(v));
    return d;
}
__device__ __forceinline__ ull pack2(float lo, float hi) {
    ull d;
    asm("mov.b64 %0, {%1, %2};" : "=l"(d) : "f"(lo), "f"(hi));
    return d;
}
__device__ __forceinline__ void unpack2(ull p, float& lo, float& hi) {
    asm("mov.b64 {%0, %1}, %2;" : "=f"(lo), "=f"(hi) : "l"(p));
}

// ---------------- kernel 1: zero small scratch ----------------
__global__ void zero_kernel(int n_graphs) {
    int i = blockIdx.x * blockDim.x + threadIdx.x;
    if (i < NPAD) g_cnt[i] = 0;
    if (i < 2 * HID) g_stats[i] = 0.f;
    if (i < n_graphs * HID) g_gsum[i] = 0.f;
    if (i < n_graphs) g_gcnt[i] = 0;
    if (i == 0) g_done = 0;
}

// ---------------- kernel 2: dst histogram + g_agg -inf init + per-node u ----------------
__global__ void hist_kernel(const int* __restrict__ ei,
                            const float* __restrict__ x,
                            const float* __restrict__ W1,
                            const float* __restrict__ b1,
                            int E, int n_nodes) {
    __shared__ float sAmB[IN_DIM * HID];   // A - B  (W1 rows 0..3 minus rows 4..7)
    __shared__ float sb1[HID];
    int t = threadIdx.x;
    if (t < IN_DIM * HID) sAmB[t] = W1[t] - W1[IN_DIM * HID + t];
    if (t < HID) sb1[t] = b1[t];
    __syncthreads();

    int idx = blockIdx.x * blockDim.x + t;
    if (idx < E) atomicAdd(&g_cnt[ei[E + idx]], 1);

    const float ninf = __int_as_float(0xFF800000);
    int tot2 = n_nodes * HID / 2;
    int stride = gridDim.x * blockDim.x;
    for (int i = idx; i < tot2; i += stride)
        reinterpret_cast<float2*>(g_agg)[i] = make_float2(ninf, ninf);

    // per-node u = x@(A-B) + b1   (one thread per node)
    if (idx < n_nodes) {
        const float4 xv = __ldg(reinterpret_cast<const float4*>(x + (size_t)idx * IN_DIM));
        float* up = g_u + (size_t)idx * HID;
        #pragma unroll 8
        for (int c = 0; c < HID; c++) {
            float a = sb1[c];
            a = fmaf(xv.x, sAmB[0 * HID + c], a);
            a = fmaf(xv.y, sAmB[1 * HID + c], a);
            a = fmaf(xv.z, sAmB[2 * HID + c], a);
            a = fmaf(xv.w, sAmB[3 * HID + c], a);
            up[c] = a;
        }
    }
}

// ---------------- kernels 3-5: 3-phase exclusive scan ----------------
__global__ void scan_part_kernel(int n) {
    __shared__ int s[SCAN_BS];
    int t = threadIdx.x;
    int i = blockIdx.x * SCAN_BS + t;
    int v = (i < n) ? g_cnt[i] : 0;
    s[t] = v;
    __syncthreads();
    #pragma unroll
    for (int off = 1; off < SCAN_BS; off <<= 1) {
        int tv = (t >= off) ? s[t - off] : 0;
        __syncthreads();
        s[t] += tv;
        __syncthreads();
    }
    g_excl[i] = s[t] - v;
    if (t == SCAN_BS - 1) g_bsum[blockIdx.x] = s[t];
}

__global__ void scan_top_kernel() {
    __shared__ int s[512];
    int t = threadIdx.x;
    int v = (t < SCAN_BLOCKS) ? g_bsum[t] : 0;
    s[t] = v;
    __syncthreads();
    #pragma unroll
    for (int off = 1; off < 512; off <<= 1) {
        int tv = (t >= off) ? s[t - off] : 0;
        __syncthreads();
        s[t] += tv;
        __syncthreads();
    }
    if (t < SCAN_BLOCKS) g_bscan[t] = s[t] - v;
}

__global__ void scan_add_kernel(int n, int E) {
    int i = blockIdx.x * blockDim.x + threadIdx.x;
    if (i < n) {
        int o = g_excl[i] + g_bscan[blockIdx.x];
        g_offs[i] = o;
        g_cursor[i] = o;
    }
    if (i == 0) g_offs[n] = E;
}

// ---------------- kernel 6: scatter (src,dst) + per-block bstart search ----------------
__global__ void scatter_kernel(const int* __restrict__ ei, int E, int n_nodes) {
    int e = blockIdx.x * blockDim.x + threadIdx.x;
    if (e < E) {
        int sN = ei[e];
        int d = ei[E + e];
        int pos = atomicAdd(&g_cursor[d], 1);
        g_esorted[pos] = make_int2(sN, d);
    }
    if (threadIdx.x == 0) {
        int target = blockIdx.x * EB;
        int lo = 0, hi = n_nodes;
        while (lo < hi) {
            int mid = (lo + hi + 1) >> 1;
            if (g_offs[mid] <= target) lo = mid; else hi = mid - 1;
        }
        g_bstart[blockIdx.x] = lo;
    }
}

// ---------------- kernel 7: edge MLP (u[d] + xj@B, f32x2) + segmented max ----------------
__global__ void __launch_bounds__(EB) edge2_kernel(
    const float* __restrict__ x,
    const float* __restrict__ W1,
    const float* __restrict__ W2, const float* __restrict__ b2,
    int E, int n_nodes)
{
    __shared__ __align__(16) float sWB[IN_DIM * HID];   // B = W1 rows 4..7
    __shared__ __align__(16) float sW2[HID * HID];
    __shared__ __align__(16) float sb2[HID];
    __shared__ float sOut[EB][HID + 1];

    const int tid = threadIdx.x;
    if (tid < IN_DIM * HID) sWB[tid] = W1[IN_DIM * HID + tid];
    for (int i = tid; i < HID * HID; i += EB) sW2[i] = W2[i];
    if (tid < HID) sb2[tid] = b2[tid];
    __syncthreads();

    const int e0 = blockIdx.x * EB;
    const int e1 = min(e0 + EB, E);
    const int e  = e0 + tid;

    if (e < E) {
        const int2 sd = g_esorted[e];
        const float4 xj = __ldg(reinterpret_cast<const float4*>(x + (size_t)sd.x * IN_DIM));
        const float4* up = reinterpret_cast<const float4*>(g_u + (size_t)sd.y * HID);

        // layer 1: hp = u[d] (loaded) + xj@B
        ull hp[16];
        #pragma unroll
        for (int q = 0; q < 8; q++) {
            float4 uv = __ldg(up + q);
            hp[2 * q]     = pack2(uv.x, uv.y);
            hp[2 * q + 1] = pack2(uv.z, uv.w);
        }
        float mj[4] = {xj.x, xj.y, xj.z, xj.w};
        #pragma unroll
        for (int k = 0; k < 4; k++) {
            ull md = dup2(mj[k]);
            const ulonglong2* wbp = reinterpret_cast<const ulonglong2*>(sWB + k * HID);
            #pragma unroll
            for (int q = 0; q < 8; q++) {
                ulonglong2 wv = wbp[q];
                hp[2 * q]     = fma2(md, wv.x, hp[2 * q]);
                hp[2 * q + 1] = fma2(md, wv.y, hp[2 * q + 1]);
            }
        }
        float h[32];
        #pragma unroll
        for (int cc = 0; cc < 16; cc++) {
            float lo, hi;
            unpack2(hp[cc], lo, hi);
            h[2 * cc]     = fmaxf(lo, 0.f);
            h[2 * cc + 1] = fmaxf(hi, 0.f);
        }

        // layer 2
        ull op[16];
        const ulonglong2* b2p = reinterpret_cast<const ulonglong2*>(sb2);
        #pragma unroll
        for (int q = 0; q < 8; q++) {
            ulonglong2 bv = b2p[q];
            op[2 * q] = bv.x; op[2 * q + 1] = bv.y;
        }
        #pragma unroll
        for (int j = 0; j < HID; j++) {
            ull hd = dup2(h[j]);
            const ulonglong2* w2p = reinterpret_cast<const ulonglong2*>(sW2 + j * HID);
            #pragma unroll
            for (int q = 0; q < 8; q++) {
                ulonglong2 wv = w2p[q];
                op[2 * q]     = fma2(hd, wv.x, op[2 * q]);
                op[2 * q + 1] = fma2(hd, wv.y, op[2 * q + 1]);
            }
        }

        #pragma unroll
        for (int cc = 0; cc < 16; cc++) {
            float lo, hi;
            unpack2(op[cc], lo, hi);
            sOut[tid][2 * cc]     = lo;
            sOut[tid][2 * cc + 1] = hi;
        }
    }
    __syncthreads();

    // segmented max over this block's edge range
    const int c = tid & 31;
    const int w = tid >> 5;
    const int nf = g_bstart[blockIdx.x];
    for (int n = nf + w; n < n_nodes; n += 8) {
        const int on = g_offs[n];
        if (on >= e1) break;
        const int on1 = g_offs[n + 1];
        const int eb = max(on, e0);
        const int ee = min(on1, e1);
        float m = -INFINITY;
        for (int k = eb; k < ee; k++) m = fmaxf(m, sOut[k - e0][c]);
        const bool interior = (on >= e0) && (on1 <= e1);
        if (interior) {
            g_agg[(size_t)n * HID + c] = m;
        } else if (eb < ee) {
            atomicMaxFloat(&g_agg[(size_t)n * HID + c], m);
        }
    }
}

// ---------------- kernel 8: BN stats (float4 reads, sanitize on read) ----------------
__global__ void __launch_bounds__(256) stats_kernel(int n_nodes) {
    int t = threadIdx.x;
    float4 sum = make_float4(0.f, 0.f, 0.f, 0.f);
    float4 sq  = make_float4(0.f, 0.f, 0.f, 0.f);
    int tot4 = n_nodes * HID / 4;
    const float4* agg4 = reinterpret_cast<const float4*>(g_agg);
    for (int i = blockIdx.x * blockDim.x + t; i < tot4; i += gridDim.x * blockDim.x) {
        float4 v = agg4[i];
        if (!isfinite(v.x)) v.x = 0.f;
        if (!isfinite(v.y)) v.y = 0.f;
        if (!isfinite(v.z)) v.z = 0.f;
        if (!isfinite(v.w)) v.w = 0.f;
        sum.x += v.x; sum.y += v.y; sum.z += v.z; sum.w += v.w;
        sq.x += v.x * v.x; sq.y += v.y * v.y; sq.z += v.z * v.z; sq.w += v.w * v.w;
    }
    __shared__ float4 sS[256], sQ[256];
    sS[t] = sum; sQ[t] = sq;
    __syncthreads();
    #pragma unroll
    for (int s = 128; s >= 8; s >>= 1) {
        if (t < s) {
            float4 a = sS[t], b = sS[t + s];
            sS[t] = make_float4(a.x + b.x, a.y + b.y, a.z + b.z, a.w + b.w);
            float4 c = sQ[t], d = sQ[t + s];
            sQ[t] = make_float4(c.x + d.x, c.y + d.y, c.z + d.z, c.w + d.w);
        }
        __syncthreads();
    }
    if (t < 8) {
        int cb = 4 * t;
        float4 a = sS[t], c = sQ[t];
        atomicAdd(&g_stats[cb + 0], a.x); atomicAdd(&g_stats[cb + 1], a.y);
        atomicAdd(&g_stats[cb + 2], a.z); atomicAdd(&g_stats[cb + 3], a.w);
        atomicAdd(&g_stats[HID + cb + 0], c.x); atomicAdd(&g_stats[HID + cb + 1], c.y);
        atomicAdd(&g_stats[HID + cb + 2], c.z); atomicAdd(&g_stats[HID + cb + 3], c.w);
    }
}

// ---------------- kernel 9: BN fold + normalize + relu + pool + (last block) readout ----------------
__global__ void __launch_bounds__(256) pool_final_kernel(
    const int* __restrict__ batch, int n_nodes,
    const float* __restrict__ gamma, const float* __restrict__ beta,
    const float* __restrict__ Wr1, const float* __restrict__ br1,
    const float* __restrict__ Wr2, const float* __restrict__ br2,
    float* __restrict__ out, int n_graphs)
{
    const int c = threadIdx.x & 31;
    const int w = threadIdx.x >> 5;

    float inv_n = 1.f / (float)n_nodes;
    float mean = g_stats[c] * inv_n;
    float var = g_stats[HID + c] * inv_n - mean * mean;
    float sc = gamma[c] * rsqrtf(var + EPSV);
    float sh = beta[c] - mean * sc;

    int chunk = (n_nodes + gridDim.x - 1) / gridDim.x;
    int n0 = blockIdx.x * chunk;
    int n1 = min(n0 + chunk, n_nodes);

    float acc = 0.f;
    int cur = -1;
    int cnt = 0;
    for (int n = n0 + w; n < n1; n += 8) {
        int g = batch[n];
        float v = g_agg[(size_t)n * HID + c];
        if (!isfinite(v)) v = 0.f;
        v = fmaxf(v * sc + sh, 0.f);
        if (g != cur) {
            if (cur >= 0) {
                atomicAdd(&g_gsum[cur * HID + c], acc);
                if (c == 0) atomicAdd(&g_gcnt[cur], cnt);
            }
            cur = g; acc = 0.f; cnt = 0;
        }
        acc += v; cnt++;
    }
    if (cur >= 0) {
        atomicAdd(&g_gsum[cur * HID + c], acc);
        if (c == 0) atomicAdd(&g_gcnt[cur], cnt);
    }

    __shared__ int s_last;
    __threadfence();
    __syncthreads();
    if (threadIdx.x == 0) {
        int ticket = atomicAdd(&g_done, 1);
        s_last = (ticket == gridDim.x - 1);
    }
    __syncthreads();
    if (s_last) {
        __threadfence();
        int g = threadIdx.x;
        if (g < n_graphs) {
            float inv_cnt = 1.f / fmaxf((float)g_gcnt[g], 1.f);
            float p[HID];
            #pragma unroll
            for (int k = 0; k < HID; k++) p[k] = g_gsum[g * HID + k] * inv_cnt;
            float h[16];
            #pragma unroll
            for (int m = 0; m < 16; m++) {
                float a = br1[m];
                #pragma unroll
                for (int k = 0; k < HID; k++) a += p[k] * Wr1[k * 16 + m];
                h[m] = fmaxf(a, 0.f);
            }
            float o = br2[0];
            #pragma unroll
            for (int m = 0; m < 16; m++) o += h[m] * Wr2[m];
            out[g] = o;
        }
    }
}

// ---------------- launch ----------------
extern "C" void kernel_launch(void* const* d_in, const int* in_sizes, int n_in,
                              void* d_out, int out_size) {
    const float* x     = (const float*)d_in[0];
    const int*   ei    = (const int*)d_in[1];
    const int*   batch = (const int*)d_in[2];
    const float* W1    = (const float*)d_in[3];
    const float* b1    = (const float*)d_in[4];
    const float* W2    = (const float*)d_in[5];
    const float* b2    = (const float*)d_in[6];
    const float* gamma = (const float*)d_in[7];
    const float* beta  = (const float*)d_in[8];
    const float* Wr1   = (const float*)d_in[9];
    const float* br1   = (const float*)d_in[10];
    const float* Wr2   = (const float*)d_in[11];
    const float* br2   = (const float*)d_in[12];
    float* out = (float*)d_out;

    int E        = in_sizes[1] / 2;
    int n_nodes  = in_sizes[2];
    int n_graphs = out_size;
    int eblocks  = (E + EB - 1) / EB;

    zero_kernel<<<(NPAD + 255) / 256, 256>>>(n_graphs);
    hist_kernel<<<(E + 255) / 256, 256>>>(ei, x, W1, b1, E, n_nodes);
    scan_part_kernel<<<SCAN_BLOCKS, SCAN_BS>>>(n_nodes);
    scan_top_kernel<<<1, 512>>>();
    scan_add_kernel<<<SCAN_BLOCKS, SCAN_BS>>>(n_nodes, E);
    scatter_kernel<<<eblocks, EB>>>(ei, E, n_nodes);
    edge2_kernel<<<eblocks, EB>>>(x, W1, W2, b2, E, n_nodes);
    stats_kernel<<<592, 256>>>(n_nodes);
    pool_final_kernel<<<256, 256>>>(batch, n_nodes, gamma, beta, Wr1, br1, Wr2, br2, out, n_graphs);
}

// round 8
// speedup vs baseline: 1.2543x; 1.1630x over previous
#include <cuda_runtime.h>
#include <cuda_bf16.h>
#include <math.h>

#define N_NODES_MAX 100000
#define E_MAX       1600000
#define HID 32
#define IN_DIM 4
#define N_GRAPHS_MAX 64
#define EPSV 1e-5f

#define SCAN_BS 256
#define SCAN_BLOCKS ((N_NODES_MAX + SCAN_BS - 1) / SCAN_BS)   // 391
#define NPAD (SCAN_BLOCKS * SCAN_BS)                          // 100096
#define EB 256          // edges per block
#define ETH 128         // threads per edge2 block (2 edges/thread)
#define MAX_EBLOCKS ((E_MAX + EB - 1) / EB + 1)

typedef unsigned long long ull;

// ---------------- static device scratch (zero at module load) ----------------
__device__ float g_agg[N_NODES_MAX * HID];
__device__ float g_u[N_NODES_MAX * HID];
__device__ float g_stats[2 * HID];
__device__ float g_gsum[N_GRAPHS_MAX * HID];
__device__ int   g_gcnt[N_GRAPHS_MAX];
__device__ int   g_done;

__device__ int g_cnt[NPAD];
__device__ int g_offs[N_NODES_MAX + 1];
__device__ int g_cursor[NPAD];
__device__ int2 g_esorted[E_MAX];
__device__ int g_bstart[MAX_EBLOCKS];

__device__ int g_scan_flag[SCAN_BLOCKS];   // 0=invalid 1=partial 2=inclusive
__device__ int g_scan_val[SCAN_BLOCKS];
__device__ int g_scan_inc[SCAN_BLOCKS];

// ---------------- helpers ----------------
__device__ __forceinline__ void atomicMaxFloat(float* addr, float v) {
    int vi = __float_as_int(v);
    if (vi >= 0) atomicMax((int*)addr, vi);
    else         atomicMin((unsigned int*)addr, (unsigned int)vi);
}
__device__ __forceinline__ ull fma2(ull a, ull b, ull c) {
    ull d;
    asm("fma.rn.f32x2 %0, %1, %2, %3;" : "=l"(d) : "l"(a), "l"(b), "l"(c));
    return d;
}
__device__ __forceinline__ ull dup2(float v) {
    ull d;
    asm("mov.b64 %0, {%1, %1};" : "=l"(d) : "f"(v));
    return d;
}
__device__ __forceinline__ ull pack2(float lo, float hi) {
    ull d;
    asm("mov.b64 %0, {%1, %2};" : "=l"(d) : "f"(lo), "f"(hi));
    return d;
}
__device__ __forceinline__ void unpack2(ull p, float& lo, float& hi) {
    asm("mov.b64 {%0, %1}, %2;" : "=f"(lo), "=f"(hi) : "l"(p));
}

// ---------------- kernel 1: dst histogram + per-node u = x@(A-B) + b1 ----------------
__global__ void hist_kernel(const int* __restrict__ ei,
                            const float* __restrict__ x,
                            const float* __restrict__ W1,
                            const float* __restrict__ b1,
                            int E, int n_nodes) {
    __shared__ float sAmB[IN_DIM * HID];
    __shared__ float sb1[HID];
    int t = threadIdx.x;
    if (t < IN_DIM * HID) sAmB[t] = W1[t] - W1[IN_DIM * HID + t];
    if (t < HID) sb1[t] = b1[t];
    __syncthreads();

    int idx = blockIdx.x * blockDim.x + t;
    if (idx < E) atomicAdd(&g_cnt[ei[E + idx]], 1);

    if (idx < n_nodes) {
        const float4 xv = __ldg(reinterpret_cast<const float4*>(x + (size_t)idx * IN_DIM));
        float* up = g_u + (size_t)idx * HID;
        #pragma unroll 8
        for (int c = 0; c < HID; c++) {
            float a = sb1[c];
            a = fmaf(xv.x, sAmB[0 * HID + c], a);
            a = fmaf(xv.y, sAmB[1 * HID + c], a);
            a = fmaf(xv.z, sAmB[2 * HID + c], a);
            a = fmaf(xv.w, sAmB[3 * HID + c], a);
            up[c] = a;
        }
    }
}

// ---------------- kernel 2: single-pass scan, warp-parallel lookback ----------------
__global__ void __launch_bounds__(SCAN_BS) scan_kernel(int n, int E) {
    __shared__ int s[SCAN_BS];
    __shared__ int s_prefix;
    const int t = threadIdx.x, b = blockIdx.x;
    int i = b * SCAN_BS + t;
    int v = (i < n) ? g_cnt[i] : 0;
    s[t] = v;
    if (t == 0) s_prefix = 0;
    __syncthreads();
    #pragma unroll
    for (int off = 1; off < SCAN_BS; off <<= 1) {
        int tv = (t >= off) ? s[t - off] : 0;
        __syncthreads();
        s[t] += tv;
        __syncthreads();
    }
    int total = s[SCAN_BS - 1];

    if (b == 0) {
        if (t == 0) {
            g_scan_inc[0] = total;
            __threadfence();
            g_scan_flag[0] = 2;
        }
    } else if (t < 32) {
        if (t == 0) {
            g_scan_val[b] = total;
            __threadfence();
            g_scan_flag[b] = 1;
        }
        __syncwarp();
        int sum = 0;
        int p = b - 1;
        while (true) {
            int idx2 = p - t;                         // lane t inspects block idx2
            int f;
            do {
                f = (idx2 >= 0) ? ((volatile int*)g_scan_flag)[idx2] : 2;
            } while (__any_sync(0xffffffffu, f == 0));
            __threadfence();
            int val = 0;
            if (idx2 >= 0)
                val = (f == 2) ? ((volatile int*)g_scan_inc)[idx2]
                               : ((volatile int*)g_scan_val)[idx2];
            unsigned m2 = __ballot_sync(0xffffffffu, f == 2);
            int firstInc = __ffs(m2) - 1;             // lowest lane (= nearest pred) with inclusive
            int contrib = (firstInc >= 0 && t > firstInc) ? 0 : val;
            #pragma unroll
            for (int o = 16; o > 0; o >>= 1)
                contrib += __shfl_down_sync(0xffffffffu, contrib, o);
            if (t == 0) sum += contrib;
            if (firstInc >= 0) break;
            p -= 32;
        }
        if (t == 0) {
            g_scan_inc[b] = sum + total;
            __threadfence();
            g_scan_flag[b] = 2;
            s_prefix = sum;
        }
    }
    __syncthreads();
    int excl = s_prefix + s[t] - v;
    if (i < n) { g_offs[i] = excl; g_cursor[i] = excl; }
    if (i == 0) g_offs[n] = E;
}

// ---------------- kernel 3: scatter + bstart + straddle-node -inf init ----------------
__global__ void scatter_kernel(const int* __restrict__ ei, int E, int n_nodes) {
    int e = blockIdx.x * blockDim.x + threadIdx.x;
    if (e < E) {
        int sN = ei[e];
        int d = ei[E + e];
        int pos = atomicAdd(&g_cursor[d], 1);
        g_esorted[pos] = make_int2(sN, d);
    }
    if (threadIdx.x == 0) {
        int target = blockIdx.x * EB;
        int lo = 0, hi = n_nodes;
        while (lo < hi) {
            int mid = (lo + hi + 1) >> 1;
            if (g_offs[mid] <= target) lo = mid; else hi = mid - 1;
        }
        g_bstart[blockIdx.x] = lo;
        if (g_offs[lo] < target) {              // node lo straddles this block boundary
            const float ninf = __int_as_float(0xFF800000);
            float* row = g_agg + (size_t)lo * HID;
            #pragma unroll
            for (int c = 0; c < HID; c++) row[c] = ninf;
        }
    }
}

// ---------------- kernel 4 (PROFILED SLOT): edge MLP, 2 edges/thread + segmented max --------
__global__ void __launch_bounds__(ETH) edge2_kernel(
    const float* __restrict__ x,
    const float* __restrict__ W1,
    const float* __restrict__ W2, const float* __restrict__ b2,
    int E, int n_nodes)
{
    __shared__ __align__(16) float sWB[IN_DIM * HID];
    __shared__ __align__(16) float sW2[HID * HID];
    __shared__ __align__(16) float sb2[HID];
    __shared__ float sOut[EB][HID + 1];

    const int tid = threadIdx.x;
    if (tid < IN_DIM * HID) sWB[tid] = W1[IN_DIM * HID + tid];
    for (int i = tid; i < HID * HID; i += ETH) sW2[i] = W2[i];
    if (tid < HID) sb2[tid] = b2[tid];
    __syncthreads();

    const int e0 = blockIdx.x * EB;
    const int e1 = min(e0 + EB, E);
    const int eA = e0 + tid;
    const int eB2 = e0 + ETH + tid;
    const bool vA = eA < E, vB = eB2 < E;

    const int2 sdA = vA ? g_esorted[eA]  : make_int2(0, 0);
    const int2 sdB = vB ? g_esorted[eB2] : make_int2(0, 0);
    const float4 xjA = __ldg(reinterpret_cast<const float4*>(x + (size_t)sdA.x * IN_DIM));
    const float4 xjB = __ldg(reinterpret_cast<const float4*>(x + (size_t)sdB.x * IN_DIM));
    const float4* upA = reinterpret_cast<const float4*>(g_u + (size_t)sdA.y * HID);
    const float4* upB = reinterpret_cast<const float4*>(g_u + (size_t)sdB.y * HID);

    // layer 1: hp = u[dst] + xj@B
    ull hpA[16], hpB[16];
    #pragma unroll
    for (int q = 0; q < 8; q++) {
        float4 ua = __ldg(upA + q);
        hpA[2 * q] = pack2(ua.x, ua.y); hpA[2 * q + 1] = pack2(ua.z, ua.w);
        float4 ub = __ldg(upB + q);
        hpB[2 * q] = pack2(ub.x, ub.y); hpB[2 * q + 1] = pack2(ub.z, ub.w);
    }
    const float mjA[4] = {xjA.x, xjA.y, xjA.z, xjA.w};
    const float mjB[4] = {xjB.x, xjB.y, xjB.z, xjB.w};
    #pragma unroll
    for (int k = 0; k < 4; k++) {
        ull mdA = dup2(mjA[k]), mdB = dup2(mjB[k]);
        const ulonglong2* wbp = reinterpret_cast<const ulonglong2*>(sWB + k * HID);
        #pragma unroll
        for (int q = 0; q < 8; q++) {
            ulonglong2 wv = wbp[q];
            hpA[2 * q]     = fma2(mdA, wv.x, hpA[2 * q]);
            hpA[2 * q + 1] = fma2(mdA, wv.y, hpA[2 * q + 1]);
            hpB[2 * q]     = fma2(mdB, wv.x, hpB[2 * q]);
            hpB[2 * q + 1] = fma2(mdB, wv.y, hpB[2 * q + 1]);
        }
    }
    float hA[HID], hB[HID];
    #pragma unroll
    for (int cc = 0; cc < 16; cc++) {
        float lo, hi;
        unpack2(hpA[cc], lo, hi);
        hA[2 * cc] = fmaxf(lo, 0.f); hA[2 * cc + 1] = fmaxf(hi, 0.f);
        unpack2(hpB[cc], lo, hi);
        hB[2 * cc] = fmaxf(lo, 0.f); hB[2 * cc + 1] = fmaxf(hi, 0.f);
    }

    // layer 2: shared weight loads serve both edges
    ull opA[16], opB[16];
    const ulonglong2* b2p = reinterpret_cast<const ulonglong2*>(sb2);
    #pragma unroll
    for (int q = 0; q < 8; q++) {
        ulonglong2 bv = b2p[q];
        opA[2 * q] = bv.x; opA[2 * q + 1] = bv.y;
        opB[2 * q] = bv.x; opB[2 * q + 1] = bv.y;
    }
    #pragma unroll
    for (int j = 0; j < HID; j++) {
        ull hdA = dup2(hA[j]), hdB = dup2(hB[j]);
        const ulonglong2* w2p = reinterpret_cast<const ulonglong2*>(sW2 + j * HID);
        #pragma unroll
        for (int q = 0; q < 8; q++) {
            ulonglong2 wv = w2p[q];
            opA[2 * q]     = fma2(hdA, wv.x, opA[2 * q]);
            opA[2 * q + 1] = fma2(hdA, wv.y, opA[2 * q + 1]);
            opB[2 * q]     = fma2(hdB, wv.x, opB[2 * q]);
            opB[2 * q + 1] = fma2(hdB, wv.y, opB[2 * q + 1]);
        }
    }

    #pragma unroll
    for (int cc = 0; cc < 16; cc++) {
        float lo, hi;
        unpack2(opA[cc], lo, hi);
        sOut[tid][2 * cc] = lo; sOut[tid][2 * cc + 1] = hi;
        unpack2(opB[cc], lo, hi);
        sOut[tid + ETH][2 * cc] = lo; sOut[tid + ETH][2 * cc + 1] = hi;
    }
    __syncthreads();

    // segmented max over this block's edge range (4 warps, stride 4 over nodes)
    const int c = tid & 31;
    const int w = tid >> 5;
    const int nf = g_bstart[blockIdx.x];
    for (int n = nf + w; n < n_nodes; n += 4) {
        const int on = g_offs[n];
        if (on >= e1) break;
        const int on1 = g_offs[n + 1];
        const int eb = max(on, e0);
        const int ee = min(on1, e1);
        float m = -INFINITY;
        for (int k = eb; k < ee; k++) m = fmaxf(m, sOut[k - e0][c]);
        const bool interior = (on >= e0) && (on1 <= e1);
        if (interior) {
            g_agg[(size_t)n * HID + c] = m;
        } else if (eb < ee) {
            atomicMaxFloat(&g_agg[(size_t)n * HID + c], m);
        }
    }
}

// ---------------- kernel 5: BN stats + deferred zeroing of g_cnt / scan flags ----------------
__global__ void __launch_bounds__(256) stats_kernel(int n_nodes) {
    int t = threadIdx.x;
    int gidx = blockIdx.x * blockDim.x + t;
    if (gidx < NPAD) g_cnt[gidx] = 0;            // ready for next replay
    if (gidx < SCAN_BLOCKS) g_scan_flag[gidx] = 0;

    float4 sum = make_float4(0.f, 0.f, 0.f, 0.f);
    float4 sq  = make_float4(0.f, 0.f, 0.f, 0.f);
    int tot4 = n_nodes * HID / 4;
    const float4* agg4 = reinterpret_cast<const float4*>(g_agg);
    for (int i = gidx; i < tot4; i += gridDim.x * blockDim.x) {
        float4 v = agg4[i];
        if (!isfinite(v.x)) v.x = 0.f;
        if (!isfinite(v.y)) v.y = 0.f;
        if (!isfinite(v.z)) v.z = 0.f;
        if (!isfinite(v.w)) v.w = 0.f;
        sum.x += v.x; sum.y += v.y; sum.z += v.z; sum.w += v.w;
        sq.x += v.x * v.x; sq.y += v.y * v.y; sq.z += v.z * v.z; sq.w += v.w * v.w;
    }
    __shared__ float4 sS[256], sQ[256];
    sS[t] = sum; sQ[t] = sq;
    __syncthreads();
    #pragma unroll
    for (int s = 128; s >= 8; s >>= 1) {
        if (t < s) {
            float4 a = sS[t], b = sS[t + s];
            sS[t] = make_float4(a.x + b.x, a.y + b.y, a.z + b.z, a.w + b.w);
            float4 cq = sQ[t], d = sQ[t + s];
            sQ[t] = make_float4(cq.x + d.x, cq.y + d.y, cq.z + d.z, cq.w + d.w);
        }
        __syncthreads();
    }
    if (t < 8) {
        int cb = 4 * t;
        float4 a = sS[t], cq = sQ[t];
        atomicAdd(&g_stats[cb + 0], a.x); atomicAdd(&g_stats[cb + 1], a.y);
        atomicAdd(&g_stats[cb + 2], a.z); atomicAdd(&g_stats[cb + 3], a.w);
        atomicAdd(&g_stats[HID + cb + 0], cq.x); atomicAdd(&g_stats[HID + cb + 1], cq.y);
        atomicAdd(&g_stats[HID + cb + 2], cq.z); atomicAdd(&g_stats[HID + cb + 3], cq.w);
    }
}

// ---------------- kernel 6: BN fold + pool + readout + deferred cleanup ----------------
__global__ void __launch_bounds__(256) pool_final_kernel(
    const int* __restrict__ batch, int n_nodes,
    const float* __restrict__ gamma, const float* __restrict__ beta,
    const float* __restrict__ Wr1, const float* __restrict__ br1,
    const float* __restrict__ Wr2, const float* __restrict__ br2,
    float* __restrict__ out, int n_graphs)
{
    const int c = threadIdx.x & 31;
    const int w = threadIdx.x >> 5;

    float inv_n = 1.f / (float)n_nodes;
    float mean = g_stats[c] * inv_n;
    float var = g_stats[HID + c] * inv_n - mean * mean;
    float sc = gamma[c] * rsqrtf(var + EPSV);
    float sh = beta[c] - mean * sc;

    int chunk = (n_nodes + gridDim.x - 1) / gridDim.x;
    int n0 = blockIdx.x * chunk;
    int n1 = min(n0 + chunk, n_nodes);

    float acc = 0.f;
    int cur = -1;
    int cnt = 0;
    for (int n = n0 + w; n < n1; n += 8) {
        int g = batch[n];
        float v = g_agg[(size_t)n * HID + c];
        if (!isfinite(v)) v = 0.f;
        v = fmaxf(v * sc + sh, 0.f);
        if (g != cur) {
            if (cur >= 0) {
                atomicAdd(&g_gsum[cur * HID + c], acc);
                if (c == 0) atomicAdd(&g_gcnt[cur], cnt);
            }
            cur = g; acc = 0.f; cnt = 0;
        }
        acc += v; cnt++;
    }
    if (cur >= 0) {
        atomicAdd(&g_gsum[cur * HID + c], acc);
        if (c == 0) atomicAdd(&g_gcnt[cur], cnt);
    }

    __shared__ int s_last;
    __threadfence();
    __syncthreads();
    if (threadIdx.x == 0) {
        int ticket = atomicAdd(&g_done, 1);
        s_last = (ticket == gridDim.x - 1);
    }
    __syncthreads();
    if (s_last) {
        __threadfence();
        int g = threadIdx.x;
        float o = 0.f;
        bool wr = (g < n_graphs);
        if (wr) {
            float inv_cnt = 1.f / fmaxf((float)g_gcnt[g], 1.f);
            float p[HID];
            #pragma unroll
            for (int k = 0; k < HID; k++) p[k] = g_gsum[g * HID + k] * inv_cnt;
            float h[16];
            #pragma unroll
            for (int m = 0; m < 16; m++) {
                float a = br1[m];
                #pragma unroll
                for (int k = 0; k < HID; k++) a += p[k] * Wr1[k * 16 + m];
                h[m] = fmaxf(a, 0.f);
            }
            o = br2[0];
            #pragma unroll
            for (int m = 0; m < 16; m++) o += h[m] * Wr2[m];
        }
        __syncthreads();                 // all g_gsum/g_gcnt reads complete
        if (wr) out[g] = o;
        // deferred cleanup for next replay
        for (int i = threadIdx.x; i < N_GRAPHS_MAX * HID; i += blockDim.x) g_gsum[i] = 0.f;
        if (threadIdx.x < N_GRAPHS_MAX) g_gcnt[threadIdx.x] = 0;
        if (threadIdx.x < 2 * HID) g_stats[threadIdx.x] = 0.f;
        if (threadIdx.x == 0) g_done = 0;
    }
}

// ---------------- launch ----------------
extern "C" void kernel_launch(void* const* d_in, const int* in_sizes, int n_in,
                              void* d_out, int out_size) {
    const float* x     = (const float*)d_in[0];
    const int*   ei    = (const int*)d_in[1];
    const int*   batch = (const int*)d_in[2];
    const float* W1    = (const float*)d_in[3];
    const float* b1    = (const float*)d_in[4];
    const float* W2    = (const float*)d_in[5];
    const float* b2    = (const float*)d_in[6];
    const float* gamma = (const float*)d_in[7];
    const float* beta  = (const float*)d_in[8];
    const float* Wr1   = (const float*)d_in[9];
    const float* br1   = (const float*)d_in[10];
    const float* Wr2   = (const float*)d_in[11];
    const float* br2   = (const float*)d_in[12];
    float* out = (float*)d_out;

    int E        = in_sizes[1] / 2;
    int n_nodes  = in_sizes[2];
    int n_graphs = out_size;
    int eblocks  = (E + EB - 1) / EB;

    hist_kernel<<<(E + 255) / 256, 256>>>(ei, x, W1, b1, E, n_nodes);
    scan_kernel<<<SCAN_BLOCKS, SCAN_BS>>>(n_nodes, E);
    scatter_kernel<<<eblocks, 256>>>(ei, E, n_nodes);
    edge2_kernel<<<eblocks, ETH>>>(x, W1, W2, b2, E, n_nodes);
    stats_kernel<<<592, 256>>>(n_nodes);
    pool_final_kernel<<<256, 256>>>(batch, n_nodes, gamma, beta, Wr1, br1, Wr2, br2, out, n_graphs);
}

// round 9
// speedup vs baseline: 1.3943x; 1.1116x over previous
#include <cuda_runtime.h>
#include <cuda_bf16.h>
#include <math.h>

#define N_NODES_MAX 100000
#define E_MAX       1600000
#define HID 32
#define IN_DIM 4
#define N_GRAPHS_MAX 64
#define EPSV 1e-5f

#define SCAN_BS 256
#define SCAN_BLOCKS ((N_NODES_MAX + SCAN_BS - 1) / SCAN_BS)   // 391
#define NPAD (SCAN_BLOCKS * SCAN_BS)                          // 100096
#define EB 256          // edges per block
#define ETH 128         // threads per edge2 block (2 edges/thread)
#define SOUT_W (HID + 4)                                      // 36 words: 16B-aligned rows, conflict-free
#define MAX_EBLOCKS ((E_MAX + EB - 1) / EB + 1)

typedef unsigned long long ull;

// ---------------- static device scratch (zero at module load) ----------------
__device__ float g_agg[N_NODES_MAX * HID];
__device__ float g_stats[2 * HID];
__device__ float g_gsum[N_GRAPHS_MAX * HID];
__device__ int   g_gcnt[N_GRAPHS_MAX];
__device__ int   g_done;

__device__ int g_cnt[NPAD];
__device__ int g_offs[N_NODES_MAX + 1];
__device__ int g_cursor[NPAD];
__device__ int2 g_esorted[E_MAX];
__device__ int g_bstart[MAX_EBLOCKS];

__device__ int g_scan_flag[SCAN_BLOCKS];   // 0=invalid 1=partial 2=inclusive
__device__ int g_scan_val[SCAN_BLOCKS];
__device__ int g_scan_inc[SCAN_BLOCKS];

// ---------------- helpers ----------------
__device__ __forceinline__ void atomicMaxFloat(float* addr, float v) {
    int vi = __float_as_int(v);
    if (vi >= 0) atomicMax((int*)addr, vi);
    else         atomicMin((unsigned int*)addr, (unsigned int)vi);
}
__device__ __forceinline__ ull fma2(ull a, ull b, ull c) {
    ull d;
    asm("fma.rn.f32x2 %0, %1, %2, %3;" : "=l"(d) : "l"(a), "l"(b), "l"(c));
    return d;
}
__device__ __forceinline__ ull dup2(float v) {
    ull d;
    asm("mov.b64 %0, {%1, %1};" : "=l"(d) : "f"(v));
    return d;
}
__device__ __forceinline__ void unpack2(ull p, float& lo, float& hi) {
    asm("mov.b64 {%0, %1}, %2;" : "=f"(lo), "=f"(hi) : "l"(p));
}

// ---------------- kernel 1: dst histogram ----------------
__global__ void hist_kernel(const int* __restrict__ ei, int E) {
    int idx = blockIdx.x * blockDim.x + threadIdx.x;
    if (idx < E) atomicAdd(&g_cnt[ei[E + idx]], 1);
}

// ---------------- kernel 2: single-pass scan, warp-parallel lookback ----------------
__global__ void __launch_bounds__(SCAN_BS) scan_kernel(int n, int E) {
    __shared__ int s[SCAN_BS];
    __shared__ int s_prefix;
    const int t = threadIdx.x, b = blockIdx.x;
    int i = b * SCAN_BS + t;
    int v = (i < n) ? g_cnt[i] : 0;
    s[t] = v;
    if (t == 0) s_prefix = 0;
    __syncthreads();
    #pragma unroll
    for (int off = 1; off < SCAN_BS; off <<= 1) {
        int tv = (t >= off) ? s[t - off] : 0;
        __syncthreads();
        s[t] += tv;
        __syncthreads();
    }
    int total = s[SCAN_BS - 1];

    if (b == 0) {
        if (t == 0) {
            g_scan_inc[0] = total;
            __threadfence();
            g_scan_flag[0] = 2;
        }
    } else if (t < 32) {
        if (t == 0) {
            g_scan_val[b] = total;
            __threadfence();
            g_scan_flag[b] = 1;
        }
        __syncwarp();
        int sum = 0;
        int p = b - 1;
        while (true) {
            int idx2 = p - t;
            int f;
            do {
                f = (idx2 >= 0) ? ((volatile int*)g_scan_flag)[idx2] : 2;
            } while (__any_sync(0xffffffffu, f == 0));
            __threadfence();
            int val = 0;
            if (idx2 >= 0)
                val = (f == 2) ? ((volatile int*)g_scan_inc)[idx2]
                               : ((volatile int*)g_scan_val)[idx2];
            unsigned m2 = __ballot_sync(0xffffffffu, f == 2);
            int firstInc = __ffs(m2) - 1;
            int contrib = (firstInc >= 0 && t > firstInc) ? 0 : val;
            #pragma unroll
            for (int o = 16; o > 0; o >>= 1)
                contrib += __shfl_down_sync(0xffffffffu, contrib, o);
            if (t == 0) sum += contrib;
            if (firstInc >= 0) break;
            p -= 32;
        }
        if (t == 0) {
            g_scan_inc[b] = sum + total;
            __threadfence();
            g_scan_flag[b] = 2;
            s_prefix = sum;
        }
    }
    __syncthreads();
    int excl = s_prefix + s[t] - v;
    if (i < n) { g_offs[i] = excl; g_cursor[i] = excl; }
    if (i == 0) g_offs[n] = E;
}

// ---------------- kernel 3: scatter + bstart + straddle-node -inf init ----------------
__global__ void scatter_kernel(const int* __restrict__ ei, int E, int n_nodes) {
    int e = blockIdx.x * blockDim.x + threadIdx.x;
    if (e < E) {
        int sN = ei[e];
        int d = ei[E + e];
        int pos = atomicAdd(&g_cursor[d], 1);
        g_esorted[pos] = make_int2(sN, d);
    }
    if (threadIdx.x == 0) {
        int target = blockIdx.x * EB;
        int lo = 0, hi = n_nodes;
        while (lo < hi) {
            int mid = (lo + hi + 1) >> 1;
            if (g_offs[mid] <= target) lo = mid; else hi = mid - 1;
        }
        g_bstart[blockIdx.x] = lo;
        if (g_offs[lo] < target) {
            const float ninf = __int_as_float(0xFF800000);
            float* row = g_agg + (size_t)lo * HID;
            #pragma unroll
            for (int c = 0; c < HID; c++) row[c] = ninf;
        }
    }
}

// ---------------- kernel 4 (PROFILED SLOT): edge MLP + segmented max ----------------
__global__ void __launch_bounds__(ETH) edge2_kernel(
    const float* __restrict__ x,
    const float* __restrict__ W1, const float* __restrict__ b1,
    const float* __restrict__ W2, const float* __restrict__ b2,
    int E, int n_nodes)
{
    __shared__ __align__(16) float sW1[2 * IN_DIM * HID];
    __shared__ __align__(16) float sW2[HID * HID];
    __shared__ __align__(16) float sb1[HID];
    __shared__ __align__(16) float sb2[HID];
    __shared__ __align__(16) float sOut[EB][SOUT_W];

    const int tid = threadIdx.x;
    for (int i = tid; i < 2 * IN_DIM * HID; i += ETH) sW1[i] = W1[i];
    for (int i = tid; i < HID * HID; i += ETH)        sW2[i] = W2[i];
    if (tid < HID) { sb1[tid] = b1[tid]; sb2[tid] = b2[tid]; }
    __syncthreads();

    const int e0 = blockIdx.x * EB;
    const int e1 = min(e0 + EB, E);
    const int eA = e0 + tid;
    const int eB2 = e0 + ETH + tid;

    const int2 sdA = (eA  < E) ? g_esorted[eA]  : make_int2(0, 0);
    const int2 sdB = (eB2 < E) ? g_esorted[eB2] : make_int2(0, 0);
    const float4 xiA = __ldg(reinterpret_cast<const float4*>(x + (size_t)sdA.y * IN_DIM));
    const float4 xjA = __ldg(reinterpret_cast<const float4*>(x + (size_t)sdA.x * IN_DIM));
    const float4 xiB = __ldg(reinterpret_cast<const float4*>(x + (size_t)sdB.y * IN_DIM));
    const float4 xjB = __ldg(reinterpret_cast<const float4*>(x + (size_t)sdB.x * IN_DIM));

    float msgA[8], msgB[8];
    msgA[0] = xiA.x; msgA[1] = xiA.y; msgA[2] = xiA.z; msgA[3] = xiA.w;
    msgA[4] = xjA.x - xiA.x; msgA[5] = xjA.y - xiA.y; msgA[6] = xjA.z - xiA.z; msgA[7] = xjA.w - xiA.w;
    msgB[0] = xiB.x; msgB[1] = xiB.y; msgB[2] = xiB.z; msgB[3] = xiB.w;
    msgB[4] = xjB.x - xiB.x; msgB[5] = xjB.y - xiB.y; msgB[6] = xjB.z - xiB.z; msgB[7] = xjB.w - xiB.w;

    // layer 1: hp = b1 + msg @ W1   (shared weight loads serve both edges)
    ull hpA[16], hpB[16];
    const ulonglong2* b1p = reinterpret_cast<const ulonglong2*>(sb1);
    #pragma unroll
    for (int q = 0; q < 8; q++) {
        ulonglong2 bv = b1p[q];
        hpA[2 * q] = bv.x; hpA[2 * q + 1] = bv.y;
        hpB[2 * q] = bv.x; hpB[2 * q + 1] = bv.y;
    }
    #pragma unroll
    for (int k = 0; k < 8; k++) {
        ull mdA = dup2(msgA[k]), mdB = dup2(msgB[k]);
        const ulonglong2* w1p = reinterpret_cast<const ulonglong2*>(sW1 + k * HID);
        #pragma unroll
        for (int q = 0; q < 8; q++) {
            ulonglong2 wv = w1p[q];
            hpA[2 * q]     = fma2(mdA, wv.x, hpA[2 * q]);
            hpA[2 * q + 1] = fma2(mdA, wv.y, hpA[2 * q + 1]);
            hpB[2 * q]     = fma2(mdB, wv.x, hpB[2 * q]);
            hpB[2 * q + 1] = fma2(mdB, wv.y, hpB[2 * q + 1]);
        }
    }
    float hA[HID], hB[HID];
    #pragma unroll
    for (int cc = 0; cc < 16; cc++) {
        float lo, hi;
        unpack2(hpA[cc], lo, hi);
        hA[2 * cc] = fmaxf(lo, 0.f); hA[2 * cc + 1] = fmaxf(hi, 0.f);
        unpack2(hpB[cc], lo, hi);
        hB[2 * cc] = fmaxf(lo, 0.f); hB[2 * cc + 1] = fmaxf(hi, 0.f);
    }

    // layer 2
    ull opA[16], opB[16];
    const ulonglong2* b2p = reinterpret_cast<const ulonglong2*>(sb2);
    #pragma unroll
    for (int q = 0; q < 8; q++) {
        ulonglong2 bv = b2p[q];
        opA[2 * q] = bv.x; opA[2 * q + 1] = bv.y;
        opB[2 * q] = bv.x; opB[2 * q + 1] = bv.y;
    }
    #pragma unroll
    for (int j = 0; j < HID; j++) {
        ull hdA = dup2(hA[j]), hdB = dup2(hB[j]);
        const ulonglong2* w2p = reinterpret_cast<const ulonglong2*>(sW2 + j * HID);
        #pragma unroll
        for (int q = 0; q < 8; q++) {
            ulonglong2 wv = w2p[q];
            opA[2 * q]     = fma2(hdA, wv.x, opA[2 * q]);
            opA[2 * q + 1] = fma2(hdA, wv.y, opA[2 * q + 1]);
            opB[2 * q]     = fma2(hdB, wv.x, opB[2 * q]);
            opB[2 * q + 1] = fma2(hdB, wv.y, opB[2 * q + 1]);
        }
    }

    // packed 16B stores: (op[2q], op[2q+1]) = 4 consecutive floats of the row
    {
        ulonglong2* rA = reinterpret_cast<ulonglong2*>(&sOut[tid][0]);
        ulonglong2* rB = reinterpret_cast<ulonglong2*>(&sOut[tid + ETH][0]);
        #pragma unroll
        for (int q = 0; q < 8; q++) {
            rA[q] = make_ulonglong2(opA[2 * q], opA[2 * q + 1]);
            rB[q] = make_ulonglong2(opB[2 * q], opB[2 * q + 1]);
        }
    }
    __syncthreads();

    // segmented max over this block's edge range (4 warps, stride 4 over nodes)
    const int c = tid & 31;
    const int w = tid >> 5;
    const int nf = g_bstart[blockIdx.x];
    for (int n = nf + w; n < n_nodes; n += 4) {
        const int on = g_offs[n];
        if (on >= e1) break;
        const int on1 = g_offs[n + 1];
        const int eb = max(on, e0);
        const int ee = min(on1, e1);
        float m = -INFINITY;
        for (int k = eb; k < ee; k++) m = fmaxf(m, sOut[k - e0][c]);
        const bool interior = (on >= e0) && (on1 <= e1);
        if (interior) {
            g_agg[(size_t)n * HID + c] = m;
        } else if (eb < ee) {
            atomicMaxFloat(&g_agg[(size_t)n * HID + c], m);
        }
    }
}

// ---------------- kernel 5: BN stats + deferred zeroing of g_cnt / scan flags ----------------
__global__ void __launch_bounds__(256) stats_kernel(int n_nodes) {
    int t = threadIdx.x;
    int gidx = blockIdx.x * blockDim.x + t;
    if (gidx < NPAD) g_cnt[gidx] = 0;
    if (gidx < SCAN_BLOCKS) g_scan_flag[gidx] = 0;

    float4 sum = make_float4(0.f, 0.f, 0.f, 0.f);
    float4 sq  = make_float4(0.f, 0.f, 0.f, 0.f);
    int tot4 = n_nodes * HID / 4;
    const float4* agg4 = reinterpret_cast<const float4*>(g_agg);
    for (int i = gidx; i < tot4; i += gridDim.x * blockDim.x) {
        float4 v = agg4[i];
        if (!isfinite(v.x)) v.x = 0.f;
        if (!isfinite(v.y)) v.y = 0.f;
        if (!isfinite(v.z)) v.z = 0.f;
        if (!isfinite(v.w)) v.w = 0.f;
        sum.x += v.x; sum.y += v.y; sum.z += v.z; sum.w += v.w;
        sq.x += v.x * v.x; sq.y += v.y * v.y; sq.z += v.z * v.z; sq.w += v.w * v.w;
    }
    __shared__ float4 sS[256], sQ[256];
    sS[t] = sum; sQ[t] = sq;
    __syncthreads();
    #pragma unroll
    for (int s = 128; s >= 8; s >>= 1) {
        if (t < s) {
            float4 a = sS[t], b = sS[t + s];
            sS[t] = make_float4(a.x + b.x, a.y + b.y, a.z + b.z, a.w + b.w);
            float4 cq = sQ[t], d = sQ[t + s];
            sQ[t] = make_float4(cq.x + d.x, cq.y + d.y, cq.z + d.z, cq.w + d.w);
        }
        __syncthreads();
    }
    if (t < 8) {
        int cb = 4 * t;
        float4 a = sS[t], cq = sQ[t];
        atomicAdd(&g_stats[cb + 0], a.x); atomicAdd(&g_stats[cb + 1], a.y);
        atomicAdd(&g_stats[cb + 2], a.z); atomicAdd(&g_stats[cb + 3], a.w);
        atomicAdd(&g_stats[HID + cb + 0], cq.x); atomicAdd(&g_stats[HID + cb + 1], cq.y);
        atomicAdd(&g_stats[HID + cb + 2], cq.z); atomicAdd(&g_stats[HID + cb + 3], cq.w);
    }
}

// ---------------- kernel 6: BN fold + pool + readout + deferred cleanup ----------------
__global__ void __launch_bounds__(256) pool_final_kernel(
    const int* __restrict__ batch, int n_nodes,
    const float* __restrict__ gamma, const float* __restrict__ beta,
    const float* __restrict__ Wr1, const float* __restrict__ br1,
    const float* __restrict__ Wr2, const float* __restrict__ br2,
    float* __restrict__ out, int n_graphs)
{
    const int c = threadIdx.x & 31;
    const int w = threadIdx.x >> 5;

    float inv_n = 1.f / (float)n_nodes;
    float mean = g_stats[c] * inv_n;
    float var = g_stats[HID + c] * inv_n - mean * mean;
    float sc = gamma[c] * rsqrtf(var + EPSV);
    float sh = beta[c] - mean * sc;

    int chunk = (n_nodes + gridDim.x - 1) / gridDim.x;
    int n0 = blockIdx.x * chunk;
    int n1 = min(n0 + chunk, n_nodes);

    float acc = 0.f;
    int cur = -1;
    int cnt = 0;
    for (int n = n0 + w; n < n1; n += 8) {
        int g = batch[n];
        float v = g_agg[(size_t)n * HID + c];
        if (!isfinite(v)) v = 0.f;
        v = fmaxf(v * sc + sh, 0.f);
        if (g != cur) {
            if (cur >= 0) {
                atomicAdd(&g_gsum[cur * HID + c], acc);
                if (c == 0) atomicAdd(&g_gcnt[cur], cnt);
            }
            cur = g; acc = 0.f; cnt = 0;
        }
        acc += v; cnt++;
    }
    if (cur >= 0) {
        atomicAdd(&g_gsum[cur * HID + c], acc);
        if (c == 0) atomicAdd(&g_gcnt[cur], cnt);
    }

    __shared__ int s_last;
    __threadfence();
    __syncthreads();
    if (threadIdx.x == 0) {
        int ticket = atomicAdd(&g_done, 1);
        s_last = (ticket == gridDim.x - 1);
    }
    __syncthreads();
    if (s_last) {
        __threadfence();
        int g = threadIdx.x;
        float o = 0.f;
        bool wr = (g < n_graphs);
        if (wr) {
            float inv_cnt = 1.f / fmaxf((float)g_gcnt[g], 1.f);
            float p[HID];
            #pragma unroll
            for (int k = 0; k < HID; k++) p[k] = g_gsum[g * HID + k] * inv_cnt;
            float h[16];
            #pragma unroll
            for (int m = 0; m < 16; m++) {
                float a = br1[m];
                #pragma unroll
                for (int k = 0; k < HID; k++) a += p[k] * Wr1[k * 16 + m];
                h[m] = fmaxf(a, 0.f);
            }
            o = br2[0];
            #pragma unroll
            for (int m = 0; m < 16; m++) o += h[m] * Wr2[m];
        }
        __syncthreads();
        if (wr) out[g] = o;
        // deferred cleanup for next replay
        for (int i = threadIdx.x; i < N_GRAPHS_MAX * HID; i += blockDim.x) g_gsum[i] = 0.f;
        if (threadIdx.x < N_GRAPHS_MAX) g_gcnt[threadIdx.x] = 0;
        if (threadIdx.x < 2 * HID) g_stats[threadIdx.x] = 0.f;
        if (threadIdx.x == 0) g_done = 0;
    }
}

// ---------------- launch ----------------
extern "C" void kernel_launch(void* const* d_in, const int* in_sizes, int n_in,
                              void* d_out, int out_size) {
    const float* x     = (const float*)d_in[0];
    const int*   ei    = (const int*)d_in[1];
    const int*   batch = (const int*)d_in[2];
    const float* W1    = (const float*)d_in[3];
    const float* b1    = (const float*)d_in[4];
    const float* W2    = (const float*)d_in[5];
    const float* b2    = (const float*)d_in[6];
    const float* gamma = (const float*)d_in[7];
    const float* beta  = (const float*)d_in[8];
    const float* Wr1   = (const float*)d_in[9];
    const float* br1   = (const float*)d_in[10];
    const float* Wr2   = (const float*)d_in[11];
    const float* br2   = (const float*)d_in[12];
    float* out = (float*)d_out;

    int E        = in_sizes[1] / 2;
    int n_nodes  = in_sizes[2];
    int n_graphs = out_size;
    int eblocks  = (E + EB - 1) / EB;

    hist_kernel<<<(E + 255) / 256, 256>>>(ei, E);
    scan_kernel<<<SCAN_BLOCKS, SCAN_BS>>>(n_nodes, E);
    scatter_kernel<<<eblocks, 256>>>(ei, E, n_nodes);
    edge2_kernel<<<eblocks, ETH>>>(x, W1, b1, W2, b2, E, n_nodes);
    stats_kernel<<<592, 256>>>(n_nodes);
    pool_final_kernel<<<256, 256>>>(batch, n_nodes, gamma, beta, Wr1, br1, Wr2, br2, out, n_graphs);
}

// round 10
// speedup vs baseline: 1.4535x; 1.0425x over previous
#include <cuda_runtime.h>
#include <cuda_bf16.h>
#include <math.h>

#define N_NODES_MAX 100000
#define E_MAX       1600000
#define HID 32
#define IN_DIM 4
#define N_GRAPHS_MAX 64
#define EPSV 1e-5f

#define SCAN_BS 256
#define SCAN_BLOCKS ((N_NODES_MAX + SCAN_BS - 1) / SCAN_BS)   // 391
#define NPAD (SCAN_BLOCKS * SCAN_BS)                          // 100096
#define EB 256          // edges per block
#define ETH 128         // threads per edge2 block (2 edges/thread)
#define BUF_W 36        // padded row width: STS.128-aligned + conflict-free frags
#define MAX_EBLOCKS ((E_MAX + EB - 1) / EB + 1)

typedef unsigned long long ull;

// ---------------- static device scratch (zero at module load) ----------------
__device__ float g_agg[N_NODES_MAX * HID];
__device__ float g_stats[2 * HID];
__device__ float g_gsum[N_GRAPHS_MAX * HID];
__device__ int   g_gcnt[N_GRAPHS_MAX];
__device__ int   g_done;

__device__ int g_cnt[NPAD];
__device__ int g_offs[N_NODES_MAX + 1];
__device__ int g_cursor[NPAD];
__device__ int2 g_esorted[E_MAX];
__device__ int g_bstart[MAX_EBLOCKS];

__device__ int g_scan_flag[SCAN_BLOCKS];   // 0=invalid 1=partial 2=inclusive
__device__ int g_scan_val[SCAN_BLOCKS];
__device__ int g_scan_inc[SCAN_BLOCKS];

// ---------------- helpers ----------------
__device__ __forceinline__ void atomicMaxFloat(float* addr, float v) {
    int vi = __float_as_int(v);
    if (vi >= 0) atomicMax((int*)addr, vi);
    else         atomicMin((unsigned int*)addr, (unsigned int)vi);
}
__device__ __forceinline__ ull fma2(ull a, ull b, ull c) {
    ull d;
    asm("fma.rn.f32x2 %0, %1, %2, %3;" : "=l"(d) : "l"(a), "l"(b), "l"(c));
    return d;
}
__device__ __forceinline__ ull dup2(float v) {
    ull d;
    asm("mov.b64 %0, {%1, %1};" : "=l"(d) : "f"(v));
    return d;
}
__device__ __forceinline__ void unpack2(ull p, float& lo, float& hi) {
    asm("mov.b64 {%0, %1}, %2;" : "=f"(lo), "=f"(hi) : "l"(p));
}
__device__ __forceinline__ unsigned f2tf(float f) {
    unsigned u;
    asm("cvt.rna.tf32.f32 %0, %1;" : "=r"(u) : "f"(f));
    return u;
}
__device__ __forceinline__ void mma_tf32(float& d0, float& d1, float& d2, float& d3,
                                         unsigned a0, unsigned a1, unsigned a2, unsigned a3,
                                         unsigned b0, unsigned b1) {
    asm volatile(
        "mma.sync.aligned.m16n8k8.row.col.f32.tf32.tf32.f32 "
        "{%0,%1,%2,%3}, {%4,%5,%6,%7}, {%8,%9}, {%0,%1,%2,%3};"
        : "+f"(d0), "+f"(d1), "+f"(d2), "+f"(d3)
        : "r"(a0), "r"(a1), "r"(a2), "r"(a3), "r"(b0), "r"(b1));
}

// ---------------- kernel 1: dst histogram ----------------
__global__ void hist_kernel(const int* __restrict__ ei, int E) {
    int idx = blockIdx.x * blockDim.x + threadIdx.x;
    if (idx < E) atomicAdd(&g_cnt[ei[E + idx]], 1);
}

// ---------------- kernel 2: single-pass scan, warp-parallel lookback ----------------
__global__ void __launch_bounds__(SCAN_BS) scan_kernel(int n, int E) {
    __shared__ int s[SCAN_BS];
    __shared__ int s_prefix;
    const int t = threadIdx.x, b = blockIdx.x;
    int i = b * SCAN_BS + t;
    int v = (i < n) ? g_cnt[i] : 0;
    s[t] = v;
    if (t == 0) s_prefix = 0;
    __syncthreads();
    #pragma unroll
    for (int off = 1; off < SCAN_BS; off <<= 1) {
        int tv = (t >= off) ? s[t - off] : 0;
        __syncthreads();
        s[t] += tv;
        __syncthreads();
    }
    int total = s[SCAN_BS - 1];

    if (b == 0) {
        if (t == 0) {
            g_scan_inc[0] = total;
            __threadfence();
            g_scan_flag[0] = 2;
        }
    } else if (t < 32) {
        if (t == 0) {
            g_scan_val[b] = total;
            __threadfence();
            g_scan_flag[b] = 1;
        }
        __syncwarp();
        int sum = 0;
        int p = b - 1;
        while (true) {
            int idx2 = p - t;
            int f;
            do {
                f = (idx2 >= 0) ? ((volatile int*)g_scan_flag)[idx2] : 2;
            } while (__any_sync(0xffffffffu, f == 0));
            __threadfence();
            int val = 0;
            if (idx2 >= 0)
                val = (f == 2) ? ((volatile int*)g_scan_inc)[idx2]
                               : ((volatile int*)g_scan_val)[idx2];
            unsigned m2 = __ballot_sync(0xffffffffu, f == 2);
            int firstInc = __ffs(m2) - 1;
            int contrib = (firstInc >= 0 && t > firstInc) ? 0 : val;
            #pragma unroll
            for (int o = 16; o > 0; o >>= 1)
                contrib += __shfl_down_sync(0xffffffffu, contrib, o);
            if (t == 0) sum += contrib;
            if (firstInc >= 0) break;
            p -= 32;
        }
        if (t == 0) {
            g_scan_inc[b] = sum + total;
            __threadfence();
            g_scan_flag[b] = 2;
            s_prefix = sum;
        }
    }
    __syncthreads();
    int excl = s_prefix + s[t] - v;
    if (i < n) { g_offs[i] = excl; g_cursor[i] = excl; }
    if (i == 0) g_offs[n] = E;
}

// ---------------- kernel 3: scatter + bstart + straddle-node -inf init ----------------
__global__ void scatter_kernel(const int* __restrict__ ei, int E, int n_nodes) {
    int e = blockIdx.x * blockDim.x + threadIdx.x;
    if (e < E) {
        int sN = ei[e];
        int d = ei[E + e];
        int pos = atomicAdd(&g_cursor[d], 1);
        g_esorted[pos] = make_int2(sN, d);
    }
    if (threadIdx.x == 0) {
        int target = blockIdx.x * EB;
        int lo = 0, hi = n_nodes;
        while (lo < hi) {
            int mid = (lo + hi + 1) >> 1;
            if (g_offs[mid] <= target) lo = mid; else hi = mid - 1;
        }
        g_bstart[blockIdx.x] = lo;
        if (g_offs[lo] < target) {
            const float ninf = __int_as_float(0xFF800000);
            float* row = g_agg + (size_t)lo * HID;
            #pragma unroll
            for (int c = 0; c < HID; c++) row[c] = ninf;
        }
    }
}

// ---------------- kernel 4 (PROFILED SLOT): layer1 fp32 + layer2 tensor-core + seg max ----
__global__ void __launch_bounds__(ETH) edge2_kernel(
    const float* __restrict__ x,
    const float* __restrict__ W1, const float* __restrict__ b1,
    const float* __restrict__ W2, const float* __restrict__ b2,
    int E, int n_nodes)
{
    __shared__ __align__(16) float sW1[2 * IN_DIM * HID];
    __shared__ __align__(16) float sW2[HID * HID];
    __shared__ __align__(16) float sb1[HID];
    __shared__ __align__(16) float sb2[HID];
    // aliased buffer: phase A holds tf32 h rows, phase B overwritten with fp32 outputs
    __shared__ __align__(16) float sBuf[EB][BUF_W];

    const int tid = threadIdx.x;
    for (int i = tid; i < 2 * IN_DIM * HID; i += ETH) sW1[i] = W1[i];
    for (int i = tid; i < HID * HID; i += ETH)        sW2[i] = W2[i];
    if (tid < HID) { sb1[tid] = b1[tid]; sb2[tid] = b2[tid]; }
    __syncthreads();

    const int e0 = blockIdx.x * EB;
    const int e1 = min(e0 + EB, E);
    const int eA = e0 + tid;
    const int eB2 = e0 + ETH + tid;

    const int2 sdA = (eA  < E) ? g_esorted[eA]  : make_int2(0, 0);
    const int2 sdB = (eB2 < E) ? g_esorted[eB2] : make_int2(0, 0);
    const float4 xiA = __ldg(reinterpret_cast<const float4*>(x + (size_t)sdA.y * IN_DIM));
    const float4 xjA = __ldg(reinterpret_cast<const float4*>(x + (size_t)sdA.x * IN_DIM));
    const float4 xiB = __ldg(reinterpret_cast<const float4*>(x + (size_t)sdB.y * IN_DIM));
    const float4 xjB = __ldg(reinterpret_cast<const float4*>(x + (size_t)sdB.x * IN_DIM));

    float msgA[8], msgB[8];
    msgA[0] = xiA.x; msgA[1] = xiA.y; msgA[2] = xiA.z; msgA[3] = xiA.w;
    msgA[4] = xjA.x - xiA.x; msgA[5] = xjA.y - xiA.y; msgA[6] = xjA.z - xiA.z; msgA[7] = xjA.w - xiA.w;
    msgB[0] = xiB.x; msgB[1] = xiB.y; msgB[2] = xiB.z; msgB[3] = xiB.w;
    msgB[4] = xjB.x - xiB.x; msgB[5] = xjB.y - xiB.y; msgB[6] = xjB.z - xiB.z; msgB[7] = xjB.w - xiB.w;

    // ---- layer 1 (exact fp32 packed) ----
    ull hpA[16], hpB[16];
    const ulonglong2* b1p = reinterpret_cast<const ulonglong2*>(sb1);
    #pragma unroll
    for (int q = 0; q < 8; q++) {
        ulonglong2 bv = b1p[q];
        hpA[2 * q] = bv.x; hpA[2 * q + 1] = bv.y;
        hpB[2 * q] = bv.x; hpB[2 * q + 1] = bv.y;
    }
    #pragma unroll
    for (int k = 0; k < 8; k++) {
        ull mdA = dup2(msgA[k]), mdB = dup2(msgB[k]);
        const ulonglong2* w1p = reinterpret_cast<const ulonglong2*>(sW1 + k * HID);
        #pragma unroll
        for (int q = 0; q < 8; q++) {
            ulonglong2 wv = w1p[q];
            hpA[2 * q]     = fma2(mdA, wv.x, hpA[2 * q]);
            hpA[2 * q + 1] = fma2(mdA, wv.y, hpA[2 * q + 1]);
            hpB[2 * q]     = fma2(mdB, wv.x, hpB[2 * q]);
            hpB[2 * q + 1] = fma2(mdB, wv.y, hpB[2 * q + 1]);
        }
    }

    // relu + tf32 round + packed 16B store of h rows tid and tid+ETH
    {
        uint4* rA = reinterpret_cast<uint4*>(&sBuf[tid][0]);
        uint4* rB = reinterpret_cast<uint4*>(&sBuf[tid + ETH][0]);
        #pragma unroll
        for (int q = 0; q < 8; q++) {
            float l0, h0, l1, h1;
            unpack2(hpA[2 * q], l0, h0);
            unpack2(hpA[2 * q + 1], l1, h1);
            rA[q] = make_uint4(f2tf(fmaxf(l0, 0.f)), f2tf(fmaxf(h0, 0.f)),
                               f2tf(fmaxf(l1, 0.f)), f2tf(fmaxf(h1, 0.f)));
            unpack2(hpB[2 * q], l0, h0);
            unpack2(hpB[2 * q + 1], l1, h1);
            rB[q] = make_uint4(f2tf(fmaxf(l0, 0.f)), f2tf(fmaxf(h0, 0.f)),
                               f2tf(fmaxf(l1, 0.f)), f2tf(fmaxf(h1, 0.f)));
        }
    }
    __syncthreads();

    // ---- layer 2: tensor core, [64x32] @ [32x32] per warp ----
    {
        const int lane = tid & 31;
        const int warp = tid >> 5;
        const int grp = lane >> 2;      // 0..7
        const int tig = lane & 3;       // 0..3

        // B fragments (W2 tf32): b[kt][nt][2]
        unsigned bf[4][4][2];
        #pragma unroll
        for (int kt = 0; kt < 4; kt++)
            #pragma unroll
            for (int nt = 0; nt < 4; nt++) {
                bf[kt][nt][0] = f2tf(sW2[(kt * 8 + tig) * HID + nt * 8 + grp]);
                bf[kt][nt][1] = f2tf(sW2[(kt * 8 + tig + 4) * HID + nt * 8 + grp]);
            }
        // bias per-thread (D cols = nt*8 + 2*tig, +1)
        float bias_lo[4], bias_hi[4];
        #pragma unroll
        for (int nt = 0; nt < 4; nt++) {
            bias_lo[nt] = sb2[nt * 8 + 2 * tig];
            bias_hi[nt] = sb2[nt * 8 + 2 * tig + 1];
        }

        const unsigned* bufU = reinterpret_cast<const unsigned*>(&sBuf[0][0]);
        const int baseRow = warp << 6;     // 64 rows per warp

        #pragma unroll
        for (int m = 0; m < 4; m++) {
            const int r0 = baseRow + m * 16 + grp;   // rows r0, r0+8
            float d[4][4];
            #pragma unroll
            for (int nt = 0; nt < 4; nt++) {
                d[nt][0] = bias_lo[nt]; d[nt][1] = bias_hi[nt];
                d[nt][2] = bias_lo[nt]; d[nt][3] = bias_hi[nt];
            }
            #pragma unroll
            for (int kt = 0; kt < 4; kt++) {
                unsigned a0 = bufU[r0 * BUF_W + kt * 8 + tig];
                unsigned a1 = bufU[(r0 + 8) * BUF_W + kt * 8 + tig];
                unsigned a2 = bufU[r0 * BUF_W + kt * 8 + tig + 4];
                unsigned a3 = bufU[(r0 + 8) * BUF_W + kt * 8 + tig + 4];
                #pragma unroll
                for (int nt = 0; nt < 4; nt++)
                    mma_tf32(d[nt][0], d[nt][1], d[nt][2], d[nt][3],
                             a0, a1, a2, a3, bf[kt][nt][0], bf[kt][nt][1]);
            }
            // store D (all A loads of this mtile already consumed -> safe to alias)
            #pragma unroll
            for (int nt = 0; nt < 4; nt++) {
                *reinterpret_cast<float2*>(&sBuf[r0][nt * 8 + 2 * tig]) =
                    make_float2(d[nt][0], d[nt][1]);
                *reinterpret_cast<float2*>(&sBuf[r0 + 8][nt * 8 + 2 * tig]) =
                    make_float2(d[nt][2], d[nt][3]);
            }
        }
    }
    __syncthreads();

    // ---- segmented max over this block's edge range (4 warps, stride 4 over nodes) ----
    const int c = tid & 31;
    const int w = tid >> 5;
    const int nf = g_bstart[blockIdx.x];
    for (int n = nf + w; n < n_nodes; n += 4) {
        const int on = g_offs[n];
        if (on >= e1) break;
        const int on1 = g_offs[n + 1];
        const int eb = max(on, e0);
        const int ee = min(on1, e1);
        float m = -INFINITY;
        for (int k = eb; k < ee; k++) m = fmaxf(m, sBuf[k - e0][c]);
        const bool interior = (on >= e0) && (on1 <= e1);
        if (interior) {
            g_agg[(size_t)n * HID + c] = m;
        } else if (eb < ee) {
            atomicMaxFloat(&g_agg[(size_t)n * HID + c], m);
        }
    }
}

// ---------------- kernel 5: BN stats + deferred zeroing of g_cnt / scan flags ----------------
__global__ void __launch_bounds__(256) stats_kernel(int n_nodes) {
    int t = threadIdx.x;
    int gidx = blockIdx.x * blockDim.x + t;
    if (gidx < NPAD) g_cnt[gidx] = 0;
    if (gidx < SCAN_BLOCKS) g_scan_flag[gidx] = 0;

    float4 sum = make_float4(0.f, 0.f, 0.f, 0.f);
    float4 sq  = make_float4(0.f, 0.f, 0.f, 0.f);
    int tot4 = n_nodes * HID / 4;
    const float4* agg4 = reinterpret_cast<const float4*>(g_agg);
    for (int i = gidx; i < tot4; i += gridDim.x * blockDim.x) {
        float4 v = agg4[i];
        if (!isfinite(v.x)) v.x = 0.f;
        if (!isfinite(v.y)) v.y = 0.f;
        if (!isfinite(v.z)) v.z = 0.f;
        if (!isfinite(v.w)) v.w = 0.f;
        sum.x += v.x; sum.y += v.y; sum.z += v.z; sum.w += v.w;
        sq.x += v.x * v.x; sq.y += v.y * v.y; sq.z += v.z * v.z; sq.w += v.w * v.w;
    }
    __shared__ float4 sS[256], sQ[256];
    sS[t] = sum; sQ[t] = sq;
    __syncthreads();
    #pragma unroll
    for (int s = 128; s >= 8; s >>= 1) {
        if (t < s) {
            float4 a = sS[t], b = sS[t + s];
            sS[t] = make_float4(a.x + b.x, a.y + b.y, a.z + b.z, a.w + b.w);
            float4 cq = sQ[t], d = sQ[t + s];
            sQ[t] = make_float4(cq.x + d.x, cq.y + d.y, cq.z + d.z, cq.w + d.w);
        }
        __syncthreads();
    }
    if (t < 8) {
        int cb = 4 * t;
        float4 a = sS[t], cq = sQ[t];
        atomicAdd(&g_stats[cb + 0], a.x); atomicAdd(&g_stats[cb + 1], a.y);
        atomicAdd(&g_stats[cb + 2], a.z); atomicAdd(&g_stats[cb + 3], a.w);
        atomicAdd(&g_stats[HID + cb + 0], cq.x); atomicAdd(&g_stats[HID + cb + 1], cq.y);
        atomicAdd(&g_stats[HID + cb + 2], cq.z); atomicAdd(&g_stats[HID + cb + 3], cq.w);
    }
}

// ---------------- kernel 6: BN fold + pool + readout + deferred cleanup ----------------
__global__ void __launch_bounds__(256) pool_final_kernel(
    const int* __restrict__ batch, int n_nodes,
    const float* __restrict__ gamma, const float* __restrict__ beta,
    const float* __restrict__ Wr1, const float* __restrict__ br1,
    const float* __restrict__ Wr2, const float* __restrict__ br2,
    float* __restrict__ out, int n_graphs)
{
    const int c = threadIdx.x & 31;
    const int w = threadIdx.x >> 5;

    float inv_n = 1.f / (float)n_nodes;
    float mean = g_stats[c] * inv_n;
    float var = g_stats[HID + c] * inv_n - mean * mean;
    float sc = gamma[c] * rsqrtf(var + EPSV);
    float sh = beta[c] - mean * sc;

    int chunk = (n_nodes + gridDim.x - 1) / gridDim.x;
    int n0 = blockIdx.x * chunk;
    int n1 = min(n0 + chunk, n_nodes);

    float acc = 0.f;
    int cur = -1;
    int cnt = 0;
    for (int n = n0 + w; n < n1; n += 8) {
        int g = batch[n];
        float v = g_agg[(size_t)n * HID + c];
        if (!isfinite(v)) v = 0.f;
        v = fmaxf(v * sc + sh, 0.f);
        if (g != cur) {
            if (cur >= 0) {
                atomicAdd(&g_gsum[cur * HID + c], acc);
                if (c == 0) atomicAdd(&g_gcnt[cur], cnt);
            }
            cur = g; acc = 0.f; cnt = 0;
        }
        acc += v; cnt++;
    }
    if (cur >= 0) {
        atomicAdd(&g_gsum[cur * HID + c], acc);
        if (c == 0) atomicAdd(&g_gcnt[cur], cnt);
    }

    __shared__ int s_last;
    __threadfence();
    __syncthreads();
    if (threadIdx.x == 0) {
        int ticket = atomicAdd(&g_done, 1);
        s_last = (ticket == gridDim.x - 1);
    }
    __syncthreads();
    if (s_last) {
        __threadfence();
        int g = threadIdx.x;
        float o = 0.f;
        bool wr = (g < n_graphs);
        if (wr) {
            float inv_cnt = 1.f / fmaxf((float)g_gcnt[g], 1.f);
            float p[HID];
            #pragma unroll
            for (int k = 0; k < HID; k++) p[k] = g_gsum[g * HID + k] * inv_cnt;
            float h[16];
            #pragma unroll
            for (int m = 0; m < 16; m++) {
                float a = br1[m];
                #pragma unroll
                for (int k = 0; k < HID; k++) a += p[k] * Wr1[k * 16 + m];
                h[m] = fmaxf(a, 0.f);
            }
            o = br2[0];
            #pragma unroll
            for (int m = 0; m < 16; m++) o += h[m] * Wr2[m];
        }
        __syncthreads();
        if (wr) out[g] = o;
        // deferred cleanup for next replay
        for (int i = threadIdx.x; i < N_GRAPHS_MAX * HID; i += blockDim.x) g_gsum[i] = 0.f;
        if (threadIdx.x < N_GRAPHS_MAX) g_gcnt[threadIdx.x] = 0;
        if (threadIdx.x < 2 * HID) g_stats[threadIdx.x] = 0.f;
        if (threadIdx.x == 0) g_done = 0;
    }
}

// ---------------- launch ----------------
extern "C" void kernel_launch(void* const* d_in, const int* in_sizes, int n_in,
                              void* d_out, int out_size) {
    const float* x     = (const float*)d_in[0];
    const int*   ei    = (const int*)d_in[1];
    const int*   batch = (const int*)d_in[2];
    const float* W1    = (const float*)d_in[3];
    const float* b1    = (const float*)d_in[4];
    const float* W2    = (const float*)d_in[5];
    const float* b2    = (const float*)d_in[6];
    const float* gamma = (const float*)d_in[7];
    const float* beta  = (const float*)d_in[8];
    const float* Wr1   = (const float*)d_in[9];
    const float* br1   = (const float*)d_in[10];
    const float* Wr2   = (const float*)d_in[11];
    const float* br2   = (const float*)d_in[12];
    float* out = (float*)d_out;

    int E        = in_sizes[1] / 2;
    int n_nodes  = in_sizes[2];
    int n_graphs = out_size;
    int eblocks  = (E + EB - 1) / EB;

    hist_kernel<<<(E + 255) / 256, 256>>>(ei, E);
    scan_kernel<<<SCAN_BLOCKS, SCAN_BS>>>(n_nodes, E);
    scatter_kernel<<<eblocks, 256>>>(ei, E, n_nodes);
    edge2_kernel<<<eblocks, ETH>>>(x, W1, b1, W2, b2, E, n_nodes);
    stats_kernel<<<592, 256>>>(n_nodes);
    pool_final_kernel<<<256, 256>>>(batch, n_nodes, gamma, beta, Wr1, br1, Wr2, br2, out, n_graphs);
}

// round 11
// speedup vs baseline: 1.4767x; 1.0160x over previous
#include <cuda_runtime.h>
#include <cuda_bf16.h>
#include <math.h>

#define N_NODES_MAX 100000
#define E_MAX       1600000
#define HID 32
#define IN_DIM 4
#define N_GRAPHS_MAX 64
#define EPSV 1e-5f

#define SCAN_BS 256
#define SCAN_BLOCKS ((N_NODES_MAX + SCAN_BS - 1) / SCAN_BS)   // 391
#define NPAD (SCAN_BLOCKS * SCAN_BS)                          // 100096
#define EB 256          // edges per block
#define ETH 128         // threads per edge2 block
#define BUF_W 36        // padded row width (words): 16B-aligned rows, conflict-free frags
#define MAX_EBLOCKS ((E_MAX + EB - 1) / EB + 1)

typedef unsigned long long ull;

// ---------------- static device scratch (zero at module load) ----------------
__device__ float g_agg[N_NODES_MAX * HID];
__device__ float g_stats[2 * HID];
__device__ float g_gsum[N_GRAPHS_MAX * HID];
__device__ int   g_gcnt[N_GRAPHS_MAX];
__device__ int   g_done;

__device__ int g_cnt[NPAD];
__device__ int g_offs[N_NODES_MAX + 1];
__device__ int g_cursor[NPAD];
__device__ int2 g_esorted[E_MAX];
__device__ int g_bstart[MAX_EBLOCKS];

__device__ int g_scan_flag[SCAN_BLOCKS];   // 0=invalid 1=partial 2=inclusive
__device__ int g_scan_val[SCAN_BLOCKS];
__device__ int g_scan_inc[SCAN_BLOCKS];

// ---------------- helpers ----------------
__device__ __forceinline__ void atomicMaxFloat(float* addr, float v) {
    int vi = __float_as_int(v);
    if (vi >= 0) atomicMax((int*)addr, vi);
    else         atomicMin((unsigned int*)addr, (unsigned int)vi);
}
__device__ __forceinline__ unsigned f2tf(float f) {
    unsigned u;
    asm("cvt.rna.tf32.f32 %0, %1;" : "=r"(u) : "f"(f));
    return u;
}
__device__ __forceinline__ void mma_tf32(float& d0, float& d1, float& d2, float& d3,
                                         unsigned a0, unsigned a1, unsigned a2, unsigned a3,
                                         unsigned b0, unsigned b1) {
    asm volatile(
        "mma.sync.aligned.m16n8k8.row.col.f32.tf32.tf32.f32 "
        "{%0,%1,%2,%3}, {%4,%5,%6,%7}, {%8,%9}, {%0,%1,%2,%3};"
        : "+f"(d0), "+f"(d1), "+f"(d2), "+f"(d3)
        : "r"(a0), "r"(a1), "r"(a2), "r"(a3), "r"(b0), "r"(b1));
}
__device__ __forceinline__ void ldmatrix_x4(unsigned& r0, unsigned& r1,
                                            unsigned& r2, unsigned& r3, unsigned addr) {
    asm volatile("ldmatrix.sync.aligned.m8n8.x4.shared.b16 {%0,%1,%2,%3}, [%4];"
                 : "=r"(r0), "=r"(r1), "=r"(r2), "=r"(r3) : "r"(addr));
}

// ---------------- kernel 1: dst histogram ----------------
__global__ void hist_kernel(const int* __restrict__ ei, int E) {
    int idx = blockIdx.x * blockDim.x + threadIdx.x;
    if (idx < E) atomicAdd(&g_cnt[ei[E + idx]], 1);
}

// ---------------- kernel 2: single-pass scan, warp-parallel lookback ----------------
__global__ void __launch_bounds__(SCAN_BS) scan_kernel(int n, int E) {
    __shared__ int s[SCAN_BS];
    __shared__ int s_prefix;
    const int t = threadIdx.x, b = blockIdx.x;
    int i = b * SCAN_BS + t;
    int v = (i < n) ? g_cnt[i] : 0;
    s[t] = v;
    if (t == 0) s_prefix = 0;
    __syncthreads();
    #pragma unroll
    for (int off = 1; off < SCAN_BS; off <<= 1) {
        int tv = (t >= off) ? s[t - off] : 0;
        __syncthreads();
        s[t] += tv;
        __syncthreads();
    }
    int total = s[SCAN_BS - 1];

    if (b == 0) {
        if (t == 0) {
            g_scan_inc[0] = total;
            __threadfence();
            g_scan_flag[0] = 2;
        }
    } else if (t < 32) {
        if (t == 0) {
            g_scan_val[b] = total;
            __threadfence();
            g_scan_flag[b] = 1;
        }
        __syncwarp();
        int sum = 0;
        int p = b - 1;
        while (true) {
            int idx2 = p - t;
            int f;
            do {
                f = (idx2 >= 0) ? ((volatile int*)g_scan_flag)[idx2] : 2;
            } while (__any_sync(0xffffffffu, f == 0));
            __threadfence();
            int val = 0;
            if (idx2 >= 0)
                val = (f == 2) ? ((volatile int*)g_scan_inc)[idx2]
                               : ((volatile int*)g_scan_val)[idx2];
            unsigned m2 = __ballot_sync(0xffffffffu, f == 2);
            int firstInc = __ffs(m2) - 1;
            int contrib = (firstInc >= 0 && t > firstInc) ? 0 : val;
            #pragma unroll
            for (int o = 16; o > 0; o >>= 1)
                contrib += __shfl_down_sync(0xffffffffu, contrib, o);
            if (t == 0) sum += contrib;
            if (firstInc >= 0) break;
            p -= 32;
        }
        if (t == 0) {
            g_scan_inc[b] = sum + total;
            __threadfence();
            g_scan_flag[b] = 2;
            s_prefix = sum;
        }
    }
    __syncthreads();
    int excl = s_prefix + s[t] - v;
    if (i < n) { g_offs[i] = excl; g_cursor[i] = excl; }
    if (i == 0) g_offs[n] = E;
}

// ---------------- kernel 3: scatter + bstart + straddle-node -inf init ----------------
__global__ void scatter_kernel(const int* __restrict__ ei, int E, int n_nodes) {
    int e = blockIdx.x * blockDim.x + threadIdx.x;
    if (e < E) {
        int sN = ei[e];
        int d = ei[E + e];
        int pos = atomicAdd(&g_cursor[d], 1);
        g_esorted[pos] = make_int2(sN, d);
    }
    if (threadIdx.x == 0) {
        int target = blockIdx.x * EB;
        int lo = 0, hi = n_nodes;
        while (lo < hi) {
            int mid = (lo + hi + 1) >> 1;
            if (g_offs[mid] <= target) lo = mid; else hi = mid - 1;
        }
        g_bstart[blockIdx.x] = lo;
        if (g_offs[lo] < target) {
            const float ninf = __int_as_float(0xFF800000);
            float* row = g_agg + (size_t)lo * HID;
            #pragma unroll
            for (int c = 0; c < HID; c++) row[c] = ninf;
        }
    }
}

// ---------------- kernel 4 (PROFILED SLOT): full-MMA edge MLP + segmented max ----------
__global__ void __launch_bounds__(ETH) edge2_kernel(
    const float* __restrict__ x,
    const float* __restrict__ W1, const float* __restrict__ b1,
    const float* __restrict__ W2, const float* __restrict__ b2,
    int E, int n_nodes)
{
    __shared__ __align__(16) float sW1[2 * IN_DIM * HID];
    __shared__ __align__(16) float sW2[HID * HID];
    __shared__ __align__(16) float sb1[HID];
    __shared__ __align__(16) float sb2[HID];
    // phase A: tf32 msg rows (cols 0..7); phase B: tf32 h rows; phase C: fp32 outputs
    __shared__ __align__(16) float sBuf[EB][BUF_W];

    const int tid = threadIdx.x;
    for (int i = tid; i < 2 * IN_DIM * HID; i += ETH) sW1[i] = W1[i];
    for (int i = tid; i < HID * HID; i += ETH)        sW2[i] = W2[i];
    if (tid < HID) { sb1[tid] = b1[tid]; sb2[tid] = b2[tid]; }

    const int e0 = blockIdx.x * EB;
    const int e1 = min(e0 + EB, E);
    const int eA = e0 + tid;
    const int eB2 = e0 + ETH + tid;

    const int2 sdA = (eA  < E) ? g_esorted[eA]  : make_int2(0, 0);
    const int2 sdB = (eB2 < E) ? g_esorted[eB2] : make_int2(0, 0);
    const float4 xiA = __ldg(reinterpret_cast<const float4*>(x + (size_t)sdA.y * IN_DIM));
    const float4 xjA = __ldg(reinterpret_cast<const float4*>(x + (size_t)sdA.x * IN_DIM));
    const float4 xiB = __ldg(reinterpret_cast<const float4*>(x + (size_t)sdB.y * IN_DIM));
    const float4 xjB = __ldg(reinterpret_cast<const float4*>(x + (size_t)sdB.x * IN_DIM));

    // msg rows (tf32) -> sBuf cols 0..7
    {
        uint4 m0 = make_uint4(f2tf(xiA.x), f2tf(xiA.y), f2tf(xiA.z), f2tf(xiA.w));
        uint4 m1 = make_uint4(f2tf(xjA.x - xiA.x), f2tf(xjA.y - xiA.y),
                              f2tf(xjA.z - xiA.z), f2tf(xjA.w - xiA.w));
        *reinterpret_cast<uint4*>(&sBuf[tid][0]) = m0;
        *reinterpret_cast<uint4*>(&sBuf[tid][4]) = m1;
        uint4 n0 = make_uint4(f2tf(xiB.x), f2tf(xiB.y), f2tf(xiB.z), f2tf(xiB.w));
        uint4 n1 = make_uint4(f2tf(xjB.x - xiB.x), f2tf(xjB.y - xiB.y),
                              f2tf(xjB.z - xiB.z), f2tf(xjB.w - xiB.w));
        *reinterpret_cast<uint4*>(&sBuf[tid + ETH][0]) = n0;
        *reinterpret_cast<uint4*>(&sBuf[tid + ETH][4]) = n1;
    }
    __syncthreads();

    // ---- per-warp [64 x 8] @ W1 -> relu -> [64 x 32] @ W2, all on tensor cores ----
    {
        const int lane = tid & 31;
        const int warp = tid >> 5;
        const int grp = lane >> 2;      // 0..7
        const int tig = lane & 3;       // 0..3

        // B fragments
        unsigned bf1[4][2];
        #pragma unroll
        for (int nt = 0; nt < 4; nt++) {
            bf1[nt][0] = f2tf(sW1[tig * HID + nt * 8 + grp]);
            bf1[nt][1] = f2tf(sW1[(tig + 4) * HID + nt * 8 + grp]);
        }
        unsigned bf2[4][4][2];
        #pragma unroll
        for (int kt = 0; kt < 4; kt++)
            #pragma unroll
            for (int nt = 0; nt < 4; nt++) {
                bf2[kt][nt][0] = f2tf(sW2[(kt * 8 + tig) * HID + nt * 8 + grp]);
                bf2[kt][nt][1] = f2tf(sW2[(kt * 8 + tig + 4) * HID + nt * 8 + grp]);
            }
        float b1lo[4], b1hi[4], b2lo[4], b2hi[4];
        #pragma unroll
        for (int nt = 0; nt < 4; nt++) {
            b1lo[nt] = sb1[nt * 8 + 2 * tig];
            b1hi[nt] = sb1[nt * 8 + 2 * tig + 1];
            b2lo[nt] = sb2[nt * 8 + 2 * tig];
            b2hi[nt] = sb2[nt * 8 + 2 * tig + 1];
        }

        // ldmatrix per-lane quadrant addressing
        const int q = lane >> 3;            // 0..3
        const int rr = lane & 7;
        const int rowOff = (q & 1) * 8 + rr;
        const int colq = (q >> 1) * 4;
        const unsigned sbase = (unsigned)__cvta_generic_to_shared(&sBuf[0][0]);
        const int baseRow = warp << 6;

        #pragma unroll
        for (int m = 0; m < 4; m++) {
            const int rowLd = baseRow + m * 16 + rowOff;
            // layer 1: A = msg (cols 0..7)
            unsigned a0, a1, a2, a3;
            ldmatrix_x4(a0, a1, a2, a3, sbase + (unsigned)((rowLd * BUF_W + colq) * 4));
            float d1[4][4];
            #pragma unroll
            for (int nt = 0; nt < 4; nt++) {
                d1[nt][0] = b1lo[nt]; d1[nt][1] = b1hi[nt];
                d1[nt][2] = b1lo[nt]; d1[nt][3] = b1hi[nt];
                mma_tf32(d1[nt][0], d1[nt][1], d1[nt][2], d1[nt][3],
                         a0, a1, a2, a3, bf1[nt][0], bf1[nt][1]);
            }
            // relu + tf32, store h (overwrites msg cols of this mtile - already consumed)
            const int r0 = baseRow + m * 16 + grp;
            #pragma unroll
            for (int nt = 0; nt < 4; nt++) {
                *reinterpret_cast<uint2*>(&sBuf[r0][nt * 8 + 2 * tig]) =
                    make_uint2(f2tf(fmaxf(d1[nt][0], 0.f)), f2tf(fmaxf(d1[nt][1], 0.f)));
                *reinterpret_cast<uint2*>(&sBuf[r0 + 8][nt * 8 + 2 * tig]) =
                    make_uint2(f2tf(fmaxf(d1[nt][2], 0.f)), f2tf(fmaxf(d1[nt][3], 0.f)));
            }
            // layer 2
            float d2[4][4];
            #pragma unroll
            for (int nt = 0; nt < 4; nt++) {
                d2[nt][0] = b2lo[nt]; d2[nt][1] = b2hi[nt];
                d2[nt][2] = b2lo[nt]; d2[nt][3] = b2hi[nt];
            }
            #pragma unroll
            for (int kt = 0; kt < 4; kt++) {
                unsigned h0, h1, h2, h3;
                ldmatrix_x4(h0, h1, h2, h3,
                            sbase + (unsigned)((rowLd * BUF_W + kt * 8 + colq) * 4));
                #pragma unroll
                for (int nt = 0; nt < 4; nt++)
                    mma_tf32(d2[nt][0], d2[nt][1], d2[nt][2], d2[nt][3],
                             h0, h1, h2, h3, bf2[kt][nt][0], bf2[kt][nt][1]);
            }
            // store outputs (after all h loads of this mtile - safe aliasing)
            #pragma unroll
            for (int nt = 0; nt < 4; nt++) {
                *reinterpret_cast<float2*>(&sBuf[r0][nt * 8 + 2 * tig]) =
                    make_float2(d2[nt][0], d2[nt][1]);
                *reinterpret_cast<float2*>(&sBuf[r0 + 8][nt * 8 + 2 * tig]) =
                    make_float2(d2[nt][2], d2[nt][3]);
            }
        }
    }
    __syncthreads();

    // ---- segmented max over this block's edge range (4 warps, stride 4 over nodes) ----
    const int c = tid & 31;
    const int w = tid >> 5;
    const int nf = g_bstart[blockIdx.x];
    for (int n = nf + w; n < n_nodes; n += 4) {
        const int on = g_offs[n];
        if (on >= e1) break;
        const int on1 = g_offs[n + 1];
        const int eb = max(on, e0);
        const int ee = min(on1, e1);
        float m = -INFINITY;
        for (int k = eb; k < ee; k++) m = fmaxf(m, sBuf[k - e0][c]);
        const bool interior = (on >= e0) && (on1 <= e1);
        if (interior) {
            g_agg[(size_t)n * HID + c] = m;
        } else if (eb < ee) {
            atomicMaxFloat(&g_agg[(size_t)n * HID + c], m);
        }
    }
}

// ---------------- kernel 5: BN stats + deferred zeroing of g_cnt / scan flags ----------------
__global__ void __launch_bounds__(256) stats_kernel(int n_nodes) {
    int t = threadIdx.x;
    int gidx = blockIdx.x * blockDim.x + t;
    if (gidx < NPAD) g_cnt[gidx] = 0;
    if (gidx < SCAN_BLOCKS) g_scan_flag[gidx] = 0;

    float4 sum = make_float4(0.f, 0.f, 0.f, 0.f);
    float4 sq  = make_float4(0.f, 0.f, 0.f, 0.f);
    int tot4 = n_nodes * HID / 4;
    const float4* agg4 = reinterpret_cast<const float4*>(g_agg);
    for (int i = gidx; i < tot4; i += gridDim.x * blockDim.x) {
        float4 v = agg4[i];
        if (!isfinite(v.x)) v.x = 0.f;
        if (!isfinite(v.y)) v.y = 0.f;
        if (!isfinite(v.z)) v.z = 0.f;
        if (!isfinite(v.w)) v.w = 0.f;
        sum.x += v.x; sum.y += v.y; sum.z += v.z; sum.w += v.w;
        sq.x += v.x * v.x; sq.y += v.y * v.y; sq.z += v.z * v.z; sq.w += v.w * v.w;
    }
    __shared__ float4 sS[256], sQ[256];
    sS[t] = sum; sQ[t] = sq;
    __syncthreads();
    #pragma unroll
    for (int s = 128; s >= 8; s >>= 1) {
        if (t < s) {
            float4 a = sS[t], b = sS[t + s];
            sS[t] = make_float4(a.x + b.x, a.y + b.y, a.z + b.z, a.w + b.w);
            float4 cq = sQ[t], d = sQ[t + s];
            sQ[t] = make_float4(cq.x + d.x, cq.y + d.y, cq.z + d.z, cq.w + d.w);
        }
        __syncthreads();
    }
    if (t < 8) {
        int cb = 4 * t;
        float4 a = sS[t], cq = sQ[t];
        atomicAdd(&g_stats[cb + 0], a.x); atomicAdd(&g_stats[cb + 1], a.y);
        atomicAdd(&g_stats[cb + 2], a.z); atomicAdd(&g_stats[cb + 3], a.w);
        atomicAdd(&g_stats[HID + cb + 0], cq.x); atomicAdd(&g_stats[HID + cb + 1], cq.y);
        atomicAdd(&g_stats[HID + cb + 2], cq.z); atomicAdd(&g_stats[HID + cb + 3], cq.w);
    }
}

// ---------------- kernel 6: BN fold + pool + readout + deferred cleanup ----------------
__global__ void __launch_bounds__(256) pool_final_kernel(
    const int* __restrict__ batch, int n_nodes,
    const float* __restrict__ gamma, const float* __restrict__ beta,
    const float* __restrict__ Wr1, const float* __restrict__ br1,
    const float* __restrict__ Wr2, const float* __restrict__ br2,
    float* __restrict__ out, int n_graphs)
{
    const int c = threadIdx.x & 31;
    const int w = threadIdx.x >> 5;

    float inv_n = 1.f / (float)n_nodes;
    float mean = g_stats[c] * inv_n;
    float var = g_stats[HID + c] * inv_n - mean * mean;
    float sc = gamma[c] * rsqrtf(var + EPSV);
    float sh = beta[c] - mean * sc;

    int chunk = (n_nodes + gridDim.x - 1) / gridDim.x;
    int n0 = blockIdx.x * chunk;
    int n1 = min(n0 + chunk, n_nodes);

    float acc = 0.f;
    int cur = -1;
    int cnt = 0;
    for (int n = n0 + w; n < n1; n += 8) {
        int g = batch[n];
        float v = g_agg[(size_t)n * HID + c];
        if (!isfinite(v)) v = 0.f;
        v = fmaxf(v * sc + sh, 0.f);
        if (g != cur) {
            if (cur >= 0) {
                atomicAdd(&g_gsum[cur * HID + c], acc);
                if (c == 0) atomicAdd(&g_gcnt[cur], cnt);
            }
            cur = g; acc = 0.f; cnt = 0;
        }
        acc += v; cnt++;
    }
    if (cur >= 0) {
        atomicAdd(&g_gsum[cur * HID + c], acc);
        if (c == 0) atomicAdd(&g_gcnt[cur], cnt);
    }

    __shared__ int s_last;
    __threadfence();
    __syncthreads();
    if (threadIdx.x == 0) {
        int ticket = atomicAdd(&g_done, 1);
        s_last = (ticket == gridDim.x - 1);
    }
    __syncthreads();
    if (s_last) {
        __threadfence();
        int g = threadIdx.x;
        float o = 0.f;
        bool wr = (g < n_graphs);
        if (wr) {
            float inv_cnt = 1.f / fmaxf((float)g_gcnt[g], 1.f);
            float p[HID];
            #pragma unroll
            for (int k = 0; k < HID; k++) p[k] = g_gsum[g * HID + k] * inv_cnt;
            float h[16];
            #pragma unroll
            for (int m = 0; m < 16; m++) {
                float a = br1[m];
                #pragma unroll
                for (int k = 0; k < HID; k++) a += p[k] * Wr1[k * 16 + m];
                h[m] = fmaxf(a, 0.f);
            }
            o = br2[0];
            #pragma unroll
            for (int m = 0; m < 16; m++) o += h[m] * Wr2[m];
        }
        __syncthreads();
        if (wr) out[g] = o;
        // deferred cleanup for next replay
        for (int i = threadIdx.x; i < N_GRAPHS_MAX * HID; i += blockDim.x) g_gsum[i] = 0.f;
        if (threadIdx.x < N_GRAPHS_MAX) g_gcnt[threadIdx.x] = 0;
        if (threadIdx.x < 2 * HID) g_stats[threadIdx.x] = 0.f;
        if (threadIdx.x == 0) g_done = 0;
    }
}

// ---------------- launch ----------------
extern "C" void kernel_launch(void* const* d_in, const int* in_sizes, int n_in,
                              void* d_out, int out_size) {
    const float* x     = (const float*)d_in[0];
    const int*   ei    = (const int*)d_in[1];
    const int*   batch = (const int*)d_in[2];
    const float* W1    = (const float*)d_in[3];
    const float* b1    = (const float*)d_in[4];
    const float* W2    = (const float*)d_in[5];
    const float* b2    = (const float*)d_in[6];
    const float* gamma = (const float*)d_in[7];
    const float* beta  = (const float*)d_in[8];
    const float* Wr1   = (const float*)d_in[9];
    const float* br1   = (const float*)d_in[10];
    const float* Wr2   = (const float*)d_in[11];
    const float* br2   = (const float*)d_in[12];
    float* out = (float*)d_out;

    int E        = in_sizes[1] / 2;
    int n_nodes  = in_sizes[2];
    int n_graphs = out_size;
    int eblocks  = (E + EB - 1) / EB;

    hist_kernel<<<(E + 255) / 256, 256>>>(ei, E);
    scan_kernel<<<SCAN_BLOCKS, SCAN_BS>>>(n_nodes, E);
    scatter_kernel<<<eblocks, 256>>>(ei, E, n_nodes);
    edge2_kernel<<<eblocks, ETH>>>(x, W1, b1, W2, b2, E, n_nodes);
    stats_kernel<<<592, 256>>>(n_nodes);
    pool_final_kernel<<<256, 256>>>(batch, n_nodes, gamma, beta, Wr1, br1, Wr2, br2, out, n_graphs);
}

// round 12
// speedup vs baseline: 1.5992x; 1.0830x over previous
#include <cuda_runtime.h>
#include <cuda_bf16.h>
#include <math.h>

#define N_NODES_MAX 100000
#define E_MAX       1600000
#define HID 32
#define IN_DIM 4
#define N_GRAPHS_MAX 64
#define EPSV 1e-5f

#define SCAN_BS 256
#define SCAN_BLOCKS ((N_NODES_MAX + SCAN_BS - 1) / SCAN_BS)   // 391
#define NPAD (SCAN_BLOCKS * SCAN_BS)                          // 100096
#define EB 256          // edges per tile
#define ETH 128         // threads per edge2 block
#define TILES 4         // tiles per edge2 block
#define BUF_W 36        // padded row width (words): 16B-aligned rows, conflict-free frags
#define MAX_EBLOCKS ((E_MAX + EB - 1) / EB + 1)

typedef unsigned long long ull;

// ---------------- static device scratch (zero at module load) ----------------
__device__ float g_agg[N_NODES_MAX * HID];
__device__ float g_stats[2 * HID];
__device__ float g_gsum[N_GRAPHS_MAX * HID];
__device__ int   g_gcnt[N_GRAPHS_MAX];
__device__ int   g_done;

__device__ int g_cnt[NPAD];
__device__ int g_offs[N_NODES_MAX + 1];
__device__ int g_cursor[NPAD];
__device__ int2 g_esorted[E_MAX];
__device__ int g_bstart[MAX_EBLOCKS];

__device__ int g_scan_flag[SCAN_BLOCKS];   // 0=invalid 1=partial 2=inclusive
__device__ int g_scan_val[SCAN_BLOCKS];
__device__ int g_scan_inc[SCAN_BLOCKS];

// ---------------- helpers ----------------
__device__ __forceinline__ void atomicMaxFloat(float* addr, float v) {
    int vi = __float_as_int(v);
    if (vi >= 0) atomicMax((int*)addr, vi);
    else         atomicMin((unsigned int*)addr, (unsigned int)vi);
}
__device__ __forceinline__ unsigned f2tf(float f) {
    unsigned u;
    asm("cvt.rna.tf32.f32 %0, %1;" : "=r"(u) : "f"(f));
    return u;
}
__device__ __forceinline__ void mma_tf32(float& d0, float& d1, float& d2, float& d3,
                                         unsigned a0, unsigned a1, unsigned a2, unsigned a3,
                                         unsigned b0, unsigned b1) {
    asm volatile(
        "mma.sync.aligned.m16n8k8.row.col.f32.tf32.tf32.f32 "
        "{%0,%1,%2,%3}, {%4,%5,%6,%7}, {%8,%9}, {%0,%1,%2,%3};"
        : "+f"(d0), "+f"(d1), "+f"(d2), "+f"(d3)
        : "r"(a0), "r"(a1), "r"(a2), "r"(a3), "r"(b0), "r"(b1));
}
__device__ __forceinline__ void ldmatrix_x4(unsigned& r0, unsigned& r1,
                                            unsigned& r2, unsigned& r3, unsigned addr) {
    asm volatile("ldmatrix.sync.aligned.m8n8.x4.shared.b16 {%0,%1,%2,%3}, [%4];"
                 : "=r"(r0), "=r"(r1), "=r"(r2), "=r"(r3) : "r"(addr));
}

// ---------------- kernel 1: dst histogram ----------------
__global__ void hist_kernel(const int* __restrict__ ei, int E) {
    int idx = blockIdx.x * blockDim.x + threadIdx.x;
    if (idx < E) atomicAdd(&g_cnt[ei[E + idx]], 1);
}

// ---------------- kernel 2: single-pass scan, warp-parallel lookback ----------------
__global__ void __launch_bounds__(SCAN_BS) scan_kernel(int n, int E) {
    __shared__ int s[SCAN_BS];
    __shared__ int s_prefix;
    const int t = threadIdx.x, b = blockIdx.x;
    int i = b * SCAN_BS + t;
    int v = (i < n) ? g_cnt[i] : 0;
    s[t] = v;
    if (t == 0) s_prefix = 0;
    __syncthreads();
    #pragma unroll
    for (int off = 1; off < SCAN_BS; off <<= 1) {
        int tv = (t >= off) ? s[t - off] : 0;
        __syncthreads();
        s[t] += tv;
        __syncthreads();
    }
    int total = s[SCAN_BS - 1];

    if (b == 0) {
        if (t == 0) {
            g_scan_inc[0] = total;
            __threadfence();
            g_scan_flag[0] = 2;
        }
    } else if (t < 32) {
        if (t == 0) {
            g_scan_val[b] = total;
            __threadfence();
            g_scan_flag[b] = 1;
        }
        __syncwarp();
        int sum = 0;
        int p = b - 1;
        while (true) {
            int idx2 = p - t;
            int f;
            do {
                f = (idx2 >= 0) ? ((volatile int*)g_scan_flag)[idx2] : 2;
            } while (__any_sync(0xffffffffu, f == 0));
            __threadfence();
            int val = 0;
            if (idx2 >= 0)
                val = (f == 2) ? ((volatile int*)g_scan_inc)[idx2]
                               : ((volatile int*)g_scan_val)[idx2];
            unsigned m2 = __ballot_sync(0xffffffffu, f == 2);
            int firstInc = __ffs(m2) - 1;
            int contrib = (firstInc >= 0 && t > firstInc) ? 0 : val;
            #pragma unroll
            for (int o = 16; o > 0; o >>= 1)
                contrib += __shfl_down_sync(0xffffffffu, contrib, o);
            if (t == 0) sum += contrib;
            if (firstInc >= 0) break;
            p -= 32;
        }
        if (t == 0) {
            g_scan_inc[b] = sum + total;
            __threadfence();
            g_scan_flag[b] = 2;
            s_prefix = sum;
        }
    }
    __syncthreads();
    int excl = s_prefix + s[t] - v;
    if (i < n) { g_offs[i] = excl; g_cursor[i] = excl; }
    if (i == 0) g_offs[n] = E;
}

// ---------------- kernel 3: scatter + bstart + straddle-node -inf init ----------------
__global__ void scatter_kernel(const int* __restrict__ ei, int E, int n_nodes) {
    int e = blockIdx.x * blockDim.x + threadIdx.x;
    if (e < E) {
        int sN = ei[e];
        int d = ei[E + e];
        int pos = atomicAdd(&g_cursor[d], 1);
        g_esorted[pos] = make_int2(sN, d);
    }
    if (threadIdx.x == 0) {
        int target = blockIdx.x * EB;
        int lo = 0, hi = n_nodes;
        while (lo < hi) {
            int mid = (lo + hi + 1) >> 1;
            if (g_offs[mid] <= target) lo = mid; else hi = mid - 1;
        }
        g_bstart[blockIdx.x] = lo;
        if (g_offs[lo] < target) {
            const float ninf = __int_as_float(0xFF800000);
            float* row = g_agg + (size_t)lo * HID;
            #pragma unroll
            for (int c = 0; c < HID; c++) row[c] = ninf;
        }
    }
}

// ---------------- kernel 4 (PROFILED SLOT): multi-tile full-MMA edge MLP + seg max ------
__global__ void __launch_bounds__(ETH) edge2_kernel(
    const float* __restrict__ x,
    const float* __restrict__ W1, const float* __restrict__ b1,
    const float* __restrict__ W2, const float* __restrict__ b2,
    int E, int n_nodes, int eblocks)
{
    __shared__ __align__(16) float sW1[2 * IN_DIM * HID];
    __shared__ __align__(16) float sW2[HID * HID];
    __shared__ __align__(16) float sb1[HID];
    __shared__ __align__(16) float sb2[HID];
    // phase A: tf32 msg rows (cols 0..7); phase B: tf32 h rows; phase C: fp32 outputs
    __shared__ __align__(16) float sBuf[EB][BUF_W];

    const int tid = threadIdx.x;
    for (int i = tid; i < 2 * IN_DIM * HID; i += ETH) sW1[i] = W1[i];
    for (int i = tid; i < HID * HID; i += ETH)        sW2[i] = W2[i];
    if (tid < HID) { sb1[tid] = b1[tid]; sb2[tid] = b2[tid]; }
    __syncthreads();

    const int lane = tid & 31;
    const int warp = tid >> 5;
    const int grp = lane >> 2;      // 0..7
    const int tig = lane & 3;       // 0..3

    // ---- hoisted B fragments + biases (amortized over TILES tiles) ----
    unsigned bf1[4][2];
    #pragma unroll
    for (int nt = 0; nt < 4; nt++) {
        bf1[nt][0] = f2tf(sW1[tig * HID + nt * 8 + grp]);
        bf1[nt][1] = f2tf(sW1[(tig + 4) * HID + nt * 8 + grp]);
    }
    unsigned bf2[4][4][2];
    #pragma unroll
    for (int kt = 0; kt < 4; kt++)
        #pragma unroll
        for (int nt = 0; nt < 4; nt++) {
            bf2[kt][nt][0] = f2tf(sW2[(kt * 8 + tig) * HID + nt * 8 + grp]);
            bf2[kt][nt][1] = f2tf(sW2[(kt * 8 + tig + 4) * HID + nt * 8 + grp]);
        }
    float b1lo[4], b1hi[4], b2lo[4], b2hi[4];
    #pragma unroll
    for (int nt = 0; nt < 4; nt++) {
        b1lo[nt] = sb1[nt * 8 + 2 * tig];
        b1hi[nt] = sb1[nt * 8 + 2 * tig + 1];
        b2lo[nt] = sb2[nt * 8 + 2 * tig];
        b2hi[nt] = sb2[nt * 8 + 2 * tig + 1];
    }

    // ldmatrix per-lane quadrant addressing
    const int q = lane >> 3;            // 0..3
    const int rr = lane & 7;
    const int rowOff = (q & 1) * 8 + rr;
    const int colq = (q >> 1) * 4;
    const unsigned sbase = (unsigned)__cvta_generic_to_shared(&sBuf[0][0]);
    const int baseRow = warp << 6;

    for (int t = 0; t < TILES; t++) {
        const int tb = blockIdx.x * TILES + t;
        if (tb >= eblocks) break;
        const int e0 = tb * EB;
        const int e1 = min(e0 + EB, E);
        const int eA = e0 + tid;
        const int eB2 = e0 + ETH + tid;

        __syncthreads();          // sBuf free (prev tile's segmax done); also covers weight staging on t=0

        const int2 sdA = (eA  < E) ? g_esorted[eA]  : make_int2(0, 0);
        const int2 sdB = (eB2 < E) ? g_esorted[eB2] : make_int2(0, 0);
        const float4 xiA = __ldg(reinterpret_cast<const float4*>(x + (size_t)sdA.y * IN_DIM));
        const float4 xjA = __ldg(reinterpret_cast<const float4*>(x + (size_t)sdA.x * IN_DIM));
        const float4 xiB = __ldg(reinterpret_cast<const float4*>(x + (size_t)sdB.y * IN_DIM));
        const float4 xjB = __ldg(reinterpret_cast<const float4*>(x + (size_t)sdB.x * IN_DIM));

        // msg rows (tf32) -> sBuf cols 0..7
        {
            uint4 m0 = make_uint4(f2tf(xiA.x), f2tf(xiA.y), f2tf(xiA.z), f2tf(xiA.w));
            uint4 m1 = make_uint4(f2tf(xjA.x - xiA.x), f2tf(xjA.y - xiA.y),
                                  f2tf(xjA.z - xiA.z), f2tf(xjA.w - xiA.w));
            *reinterpret_cast<uint4*>(&sBuf[tid][0]) = m0;
            *reinterpret_cast<uint4*>(&sBuf[tid][4]) = m1;
            uint4 n0 = make_uint4(f2tf(xiB.x), f2tf(xiB.y), f2tf(xiB.z), f2tf(xiB.w));
            uint4 n1 = make_uint4(f2tf(xjB.x - xiB.x), f2tf(xjB.y - xiB.y),
                                  f2tf(xjB.z - xiB.z), f2tf(xjB.w - xiB.w));
            *reinterpret_cast<uint4*>(&sBuf[tid + ETH][0]) = n0;
            *reinterpret_cast<uint4*>(&sBuf[tid + ETH][4]) = n1;
        }
        __syncthreads();

        // per-warp [64 x 8] @ W1 -> relu -> [64 x 32] @ W2, all on tensor cores
        #pragma unroll
        for (int m = 0; m < 4; m++) {
            const int rowLd = baseRow + m * 16 + rowOff;
            unsigned a0, a1, a2, a3;
            ldmatrix_x4(a0, a1, a2, a3, sbase + (unsigned)((rowLd * BUF_W + colq) * 4));
            float d1[4][4];
            #pragma unroll
            for (int nt = 0; nt < 4; nt++) {
                d1[nt][0] = b1lo[nt]; d1[nt][1] = b1hi[nt];
                d1[nt][2] = b1lo[nt]; d1[nt][3] = b1hi[nt];
                mma_tf32(d1[nt][0], d1[nt][1], d1[nt][2], d1[nt][3],
                         a0, a1, a2, a3, bf1[nt][0], bf1[nt][1]);
            }
            const int r0 = baseRow + m * 16 + grp;
            #pragma unroll
            for (int nt = 0; nt < 4; nt++) {
                *reinterpret_cast<uint2*>(&sBuf[r0][nt * 8 + 2 * tig]) =
                    make_uint2(f2tf(fmaxf(d1[nt][0], 0.f)), f2tf(fmaxf(d1[nt][1], 0.f)));
                *reinterpret_cast<uint2*>(&sBuf[r0 + 8][nt * 8 + 2 * tig]) =
                    make_uint2(f2tf(fmaxf(d1[nt][2], 0.f)), f2tf(fmaxf(d1[nt][3], 0.f)));
            }
            float d2[4][4];
            #pragma unroll
            for (int nt = 0; nt < 4; nt++) {
                d2[nt][0] = b2lo[nt]; d2[nt][1] = b2hi[nt];
                d2[nt][2] = b2lo[nt]; d2[nt][3] = b2hi[nt];
            }
            #pragma unroll
            for (int kt = 0; kt < 4; kt++) {
                unsigned h0, h1, h2, h3;
                ldmatrix_x4(h0, h1, h2, h3,
                            sbase + (unsigned)((rowLd * BUF_W + kt * 8 + colq) * 4));
                #pragma unroll
                for (int nt = 0; nt < 4; nt++)
                    mma_tf32(d2[nt][0], d2[nt][1], d2[nt][2], d2[nt][3],
                             h0, h1, h2, h3, bf2[kt][nt][0], bf2[kt][nt][1]);
            }
            #pragma unroll
            for (int nt = 0; nt < 4; nt++) {
                *reinterpret_cast<float2*>(&sBuf[r0][nt * 8 + 2 * tig]) =
                    make_float2(d2[nt][0], d2[nt][1]);
                *reinterpret_cast<float2*>(&sBuf[r0 + 8][nt * 8 + 2 * tig]) =
                    make_float2(d2[nt][2], d2[nt][3]);
            }
        }
        __syncthreads();

        // segmented max over this tile's edge range (4 warps, stride 4 over nodes)
        const int c = lane;
        const int nf = g_bstart[tb];
        for (int n = nf + warp; n < n_nodes; n += 4) {
            const int on = g_offs[n];
            if (on >= e1) break;
            const int on1 = g_offs[n + 1];
            const int eb = max(on, e0);
            const int ee = min(on1, e1);
            float m = -INFINITY;
            for (int k = eb; k < ee; k++) m = fmaxf(m, sBuf[k - e0][c]);
            const bool interior = (on >= e0) && (on1 <= e1);
            if (interior) {
                g_agg[(size_t)n * HID + c] = m;
            } else if (eb < ee) {
                atomicMaxFloat(&g_agg[(size_t)n * HID + c], m);
            }
        }
    }
}

// ---------------- kernel 5: BN stats + deferred zeroing of g_cnt / scan flags ----------------
__global__ void __launch_bounds__(256) stats_kernel(int n_nodes) {
    int t = threadIdx.x;
    int gidx = blockIdx.x * blockDim.x + t;
    if (gidx < NPAD) g_cnt[gidx] = 0;
    if (gidx < SCAN_BLOCKS) g_scan_flag[gidx] = 0;

    float4 sum = make_float4(0.f, 0.f, 0.f, 0.f);
    float4 sq  = make_float4(0.f, 0.f, 0.f, 0.f);
    int tot4 = n_nodes * HID / 4;
    const float4* agg4 = reinterpret_cast<const float4*>(g_agg);
    for (int i = gidx; i < tot4; i += gridDim.x * blockDim.x) {
        float4 v = agg4[i];
        if (!isfinite(v.x)) v.x = 0.f;
        if (!isfinite(v.y)) v.y = 0.f;
        if (!isfinite(v.z)) v.z = 0.f;
        if (!isfinite(v.w)) v.w = 0.f;
        sum.x += v.x; sum.y += v.y; sum.z += v.z; sum.w += v.w;
        sq.x += v.x * v.x; sq.y += v.y * v.y; sq.z += v.z * v.z; sq.w += v.w * v.w;
    }
    __shared__ float4 sS[256], sQ[256];
    sS[t] = sum; sQ[t] = sq;
    __syncthreads();
    #pragma unroll
    for (int s = 128; s >= 8; s >>= 1) {
        if (t < s) {
            float4 a = sS[t], b = sS[t + s];
            sS[t] = make_float4(a.x + b.x, a.y + b.y, a.z + b.z, a.w + b.w);
            float4 cq = sQ[t], d = sQ[t + s];
            sQ[t] = make_float4(cq.x + d.x, cq.y + d.y, cq.z + d.z, cq.w + d.w);
        }
        __syncthreads();
    }
    if (t < 8) {
        int cb = 4 * t;
        float4 a = sS[t], cq = sQ[t];
        atomicAdd(&g_stats[cb + 0], a.x); atomicAdd(&g_stats[cb + 1], a.y);
        atomicAdd(&g_stats[cb + 2], a.z); atomicAdd(&g_stats[cb + 3], a.w);
        atomicAdd(&g_stats[HID + cb + 0], cq.x); atomicAdd(&g_stats[HID + cb + 1], cq.y);
        atomicAdd(&g_stats[HID + cb + 2], cq.z); atomicAdd(&g_stats[HID + cb + 3], cq.w);
    }
}

// ---------------- kernel 6: BN fold + pool + readout + deferred cleanup ----------------
__global__ void __launch_bounds__(256) pool_final_kernel(
    const int* __restrict__ batch, int n_nodes,
    const float* __restrict__ gamma, const float* __restrict__ beta,
    const float* __restrict__ Wr1, const float* __restrict__ br1,
    const float* __restrict__ Wr2, const float* __restrict__ br2,
    float* __restrict__ out, int n_graphs)
{
    const int c = threadIdx.x & 31;
    const int w = threadIdx.x >> 5;

    float inv_n = 1.f / (float)n_nodes;
    float mean = g_stats[c] * inv_n;
    float var = g_stats[HID + c] * inv_n - mean * mean;
    float sc = gamma[c] * rsqrtf(var + EPSV);
    float sh = beta[c] - mean * sc;

    int chunk = (n_nodes + gridDim.x - 1) / gridDim.x;
    int n0 = blockIdx.x * chunk;
    int n1 = min(n0 + chunk, n_nodes);

    float acc = 0.f;
    int cur = -1;
    int cnt = 0;
    for (int n = n0 + w; n < n1; n += 8) {
        int g = batch[n];
        float v = g_agg[(size_t)n * HID + c];
        if (!isfinite(v)) v = 0.f;
        v = fmaxf(v * sc + sh, 0.f);
        if (g != cur) {
            if (cur >= 0) {
                atomicAdd(&g_gsum[cur * HID + c], acc);
                if (c == 0) atomicAdd(&g_gcnt[cur], cnt);
            }
            cur = g; acc = 0.f; cnt = 0;
        }
        acc += v; cnt++;
    }
    if (cur >= 0) {
        atomicAdd(&g_gsum[cur * HID + c], acc);
        if (c == 0) atomicAdd(&g_gcnt[cur], cnt);
    }

    __shared__ int s_last;
    __threadfence();
    __syncthreads();
    if (threadIdx.x == 0) {
        int ticket = atomicAdd(&g_done, 1);
        s_last = (ticket == gridDim.x - 1);
    }
    __syncthreads();
    if (s_last) {
        __threadfence();
        int g = threadIdx.x;
        float o = 0.f;
        bool wr = (g < n_graphs);
        if (wr) {
            float inv_cnt = 1.f / fmaxf((float)g_gcnt[g], 1.f);
            float p[HID];
            #pragma unroll
            for (int k = 0; k < HID; k++) p[k] = g_gsum[g * HID + k] * inv_cnt;
            float h[16];
            #pragma unroll
            for (int m = 0; m < 16; m++) {
                float a = br1[m];
                #pragma unroll
                for (int k = 0; k < HID; k++) a += p[k] * Wr1[k * 16 + m];
                h[m] = fmaxf(a, 0.f);
            }
            o = br2[0];
            #pragma unroll
            for (int m = 0; m < 16; m++) o += h[m] * Wr2[m];
        }
        __syncthreads();
        if (wr) out[g] = o;
        // deferred cleanup for next replay
        for (int i = threadIdx.x; i < N_GRAPHS_MAX * HID; i += blockDim.x) g_gsum[i] = 0.f;
        if (threadIdx.x < N_GRAPHS_MAX) g_gcnt[threadIdx.x] = 0;
        if (threadIdx.x < 2 * HID) g_stats[threadIdx.x] = 0.f;
        if (threadIdx.x == 0) g_done = 0;
    }
}

// ---------------- launch ----------------
extern "C" void kernel_launch(void* const* d_in, const int* in_sizes, int n_in,
                              void* d_out, int out_size) {
    const float* x     = (const float*)d_in[0];
    const int*   ei    = (const int*)d_in[1];
    const int*   batch = (const int*)d_in[2];
    const float* W1    = (const float*)d_in[3];
    const float* b1    = (const float*)d_in[4];
    const float* W2    = (const float*)d_in[5];
    const float* b2    = (const float*)d_in[6];
    const float* gamma = (const float*)d_in[7];
    const float* beta  = (const float*)d_in[8];
    const float* Wr1   = (const float*)d_in[9];
    const float* br1   = (const float*)d_in[10];
    const float* Wr2   = (const float*)d_in[11];
    const float* br2   = (const float*)d_in[12];
    float* out = (float*)d_out;

    int E        = in_sizes[1] / 2;
    int n_nodes  = in_sizes[2];
    int n_graphs = out_size;
    int eblocks  = (E + EB - 1) / EB;
    int e2blocks = (eblocks + TILES - 1) / TILES;

    hist_kernel<<<(E + 255) / 256, 256>>>(ei, E);
    scan_kernel<<<SCAN_BLOCKS, SCAN_BS>>>(n_nodes, E);
    scatter_kernel<<<eblocks, 256>>>(ei, E, n_nodes);
    edge2_kernel<<<e2blocks, ETH>>>(x, W1, b1, W2, b2, E, n_nodes, eblocks);
    stats_kernel<<<592, 256>>>(n_nodes);
    pool_final_kernel<<<256, 256>>>(batch, n_nodes, gamma, beta, Wr1, br1, Wr2, br2, out, n_graphs);
}